// round 11
// baseline (speedup 1.0000x reference)
#include <cuda_runtime.h>

// ---------------- problem constants ----------------
#define N_NODES 50000
#define E_EDGES 800000
#define TE (E_EDGES + N_NODES)   // edges + self-loops
#define IN_CH   128
#define HID2    128              // HEADS*HIDDEN = 2*64
#define OUT_CH  40
#define NEG_SLOPE 0.2f

// ---------------- scratch (device globals; NEVER touched from host) ----------
__device__ float g_h1[(size_t)N_NODES * HID2];
__device__ float g_x2[(size_t)N_NODES * HID2];
__device__ float g_h2[(size_t)N_NODES * OUT_CH];
__device__ float g_as1[N_NODES * 2];
__device__ float g_ad1[N_NODES * 2];
__device__ float g_as2[N_NODES];
__device__ float g_ad2[N_NODES];
__device__ int   g_deg[N_NODES];   // zero at load; re-zeroed by scan each call
__device__ int   g_off[N_NODES + 1];
__device__ int   g_cur[N_NODES];
__device__ int   g_csr[TE];
__device__ int   g_is64;

// ---------------- helpers ----------------
__device__ __forceinline__ float warp_sum(float v) {
    #pragma unroll
    for (int o = 16; o; o >>= 1) v += __shfl_xor_sync(0xffffffffu, v, o);
    return v;
}
__device__ __forceinline__ float lrelu(float x) {
    return x >= 0.f ? x : NEG_SLOPE * x;
}
__device__ __forceinline__ int edge_val(const void* ei, size_t idx) {
    if (g_is64) return (int)((const long long*)ei)[idx];
    return ((const int*)ei)[idx];
}

// ---------------- edge dtype detection ----------------
__global__ void k_detect(const int* __restrict__ ei32, int E) {
    int nz = 0;
    int stride = E / 64;
    for (int k = 0; k < 64; k++)
        nz |= ei32[2 * (size_t)(k * stride) + 1];
    g_is64 = (nz == 0) ? 1 : 0;
}

// ---------------- fused GEMM1 | hist ------------------------------------------
// blocks [0, G1B): gemm1 (proven R6 version: 32 nodes/block, 256 threads,
//   thread owns cols {c, c+64} x 16 rows). blocks [G1B, G1B+HB): degree histogram.
__global__ void k_gemm1_hist(const float* __restrict__ x, const float* __restrict__ W,
                             const void* __restrict__ ei,
                             int E, int total, int N, int G1B) {
    __shared__ __align__(16) float4 xs4[32][32];   // [row][k/4] (only gemm1 blocks use)
    int bid = blockIdx.x;
    if (bid < G1B) {
        int nb = bid * 32;
        const float4* xg = (const float4*)x + (size_t)nb * 32;
        for (int i = threadIdx.x; i < 32 * 32; i += 256) {
            int r = i >> 5;
            xs4[r][i & 31] = (nb + r < N) ? xg[i] : make_float4(0.f, 0.f, 0.f, 0.f);
        }
        __syncthreads();
        int col = threadIdx.x & 63;
        int rg  = threadIdx.x >> 6;
        float accA[8], accB[8];
        #pragma unroll
        for (int r = 0; r < 8; r++) { accA[r] = 0.f; accB[r] = 0.f; }
        #pragma unroll 2
        for (int k4 = 0; k4 < 32; k4++) {
            const float* Wk = W + 4 * k4 * 128;
            float a0 = Wk[col],            a1 = Wk[128 + col];
            float a2 = Wk[256 + col],      a3 = Wk[384 + col];
            float b0 = Wk[col + 64],       b1 = Wk[128 + col + 64];
            float b2 = Wk[256 + col + 64], b3 = Wk[384 + col + 64];
            #pragma unroll
            for (int r = 0; r < 8; r++) {
                float4 v = xs4[rg * 8 + r][k4];
                accA[r] += v.x * a0 + v.y * a1 + v.z * a2 + v.w * a3;
                accB[r] += v.x * b0 + v.y * b1 + v.z * b2 + v.w * b3;
            }
        }
        #pragma unroll
        for (int r = 0; r < 8; r++) {
            int nn = nb + rg * 8 + r;
            if (nn < N) {
                g_h1[(size_t)nn * 128 + col]      = accA[r];
                g_h1[(size_t)nn * 128 + col + 64] = accB[r];
            }
        }
    } else {
        // histogram of dst degrees (+ self loops)
        int t = (bid - G1B) * 256 + threadIdx.x;
        if (t >= total) return;
        int src, dst;
        if (t < E) { src = edge_val(ei, t); dst = edge_val(ei, (size_t)E + t); }
        else       { src = t - E;           dst = t - E; }
        if ((unsigned)dst >= (unsigned)N || (unsigned)src >= (unsigned)N) return;
        atomicAdd(&g_deg[dst], 1);
    }
}

// ---------------- fused scan | att1 --------------------------------------------
// block 0: exclusive scan of g_deg -> g_off/g_cur (re-zeroes g_deg).
// blocks >= 1: layer-1 attention dots, 32 warps/block, warp per node.
__global__ void k_scan_att1(const float* __restrict__ att_src,
                            const float* __restrict__ att_dst, int N) {
    __shared__ int ssum[1024];
    if (blockIdx.x == 0) {
        int t = threadIdx.x;
        int chunk = (N + 1023) / 1024;
        int s = t * chunk;
        int e = min(N, s + chunk);
        int sum = 0;
        for (int i = s; i < e; i++) sum += g_deg[i];
        ssum[t] = sum;
        __syncthreads();
        for (int o = 1; o < 1024; o <<= 1) {
            int v = (t >= o) ? ssum[t - o] : 0;
            __syncthreads();
            ssum[t] += v;
            __syncthreads();
        }
        int run = (t > 0) ? ssum[t - 1] : 0;
        for (int i = s; i < e; i++) {
            int d = g_deg[i];
            g_off[i] = run; g_cur[i] = run;
            g_deg[i] = 0;               // restore for next call
            run += d;
        }
        if (s < N && e == N) g_off[N] = run;
    } else {
        int node = (blockIdx.x - 1) * 32 + (threadIdx.x >> 5);
        int lane = threadIdx.x & 31;
        if (node >= N) return;
        float4 h = *(const float4*)(g_h1 + (size_t)node * 128 + 4 * lane);
        float4 a = *(const float4*)(att_src + 4 * lane);
        float4 d = *(const float4*)(att_dst + 4 * lane);
        float as = h.x * a.x + h.y * a.y + h.z * a.z + h.w * a.w;
        float ad = h.x * d.x + h.y * d.y + h.z * d.z + h.w * d.w;
        #pragma unroll
        for (int o = 8; o; o >>= 1) {
            as += __shfl_xor_sync(0xffffffffu, as, o);
            ad += __shfl_xor_sync(0xffffffffu, ad, o);
        }
        float as1v = __shfl_sync(0xffffffffu, as, 16);
        float ad1v = __shfl_sync(0xffffffffu, ad, 16);
        if (lane == 0) {
            g_as1[2 * node] = as; g_as1[2 * node + 1] = as1v;
            g_ad1[2 * node] = ad; g_ad1[2 * node + 1] = ad1v;
        }
    }
}

// ---------------- scatter (CSR fill) -------------------------------------------
__global__ void k_scatter(const void* __restrict__ ei, int E, int total, int N) {
    int t = blockIdx.x * blockDim.x + threadIdx.x;
    if (t >= total) return;
    int src, dst;
    if (t < E) { src = edge_val(ei, t); dst = edge_val(ei, (size_t)E + t); }
    else       { src = t - E;           dst = t - E; }
    if ((unsigned)dst >= (unsigned)N || (unsigned)src >= (unsigned)N) return;
    int pos = atomicAdd(&g_cur[dst], 1);
    g_csr[pos] = src;
}

// ---------------- aggregation layer 1 (warp per node, float4 gather) ----------
__global__ void k_agg1(const float* __restrict__ b1, int N) {
    int warp = (blockIdx.x * blockDim.x + threadIdx.x) >> 5;
    int lane = threadIdx.x & 31;
    if (warp >= N) return;
    int n = warp;
    int s = g_off[n], epn = g_off[n + 1];
    float ad0 = g_ad1[2 * n], ad1 = g_ad1[2 * n + 1];
    const float* hbase = g_h1 + 4 * lane;
    bool head0 = (lane < 16);

    float4 acc = make_float4(0.f, 0.f, 0.f, 0.f);
    float den0 = 0.f, den1 = 0.f;

    for (int j0 = s; j0 < epn; j0 += 32) {
        int j = j0 + lane;
        int sc = 0; float w0 = 0.f, w1 = 0.f;
        if (j < epn) {
            sc = g_csr[j];
            float2 as = *(const float2*)(g_as1 + 2 * sc);
            w0 = __expf(lrelu(as.x + ad0));
            w1 = __expf(lrelu(as.y + ad1));
        }
        den0 += w0; den1 += w1;
        int cnt = min(32, epn - j0);
        int i = 0;
        #define STEP(u) {                                                   \
            int   ss = __shfl_sync(0xffffffffu, sc, i + (u));               \
            float wa = __shfl_sync(0xffffffffu, w0, i + (u));               \
            float wb = __shfl_sync(0xffffffffu, w1, i + (u));               \
            float ww = head0 ? wa : wb;                                     \
            float4 v = *(const float4*)(hbase + (size_t)ss * 128);          \
            acc.x += ww * v.x; acc.y += ww * v.y;                           \
            acc.z += ww * v.z; acc.w += ww * v.w; }
        for (; i + 8 <= cnt; i += 8) {
            STEP(0) STEP(1) STEP(2) STEP(3) STEP(4) STEP(5) STEP(6) STEP(7)
        }
        for (; i < cnt; i++) { STEP(0) }
        #undef STEP
    }
    den0 = warp_sum(den0) + 1e-16f;
    den1 = warp_sum(den1) + 1e-16f;
    float den = head0 ? den0 : den1;

    float4 bb = *(const float4*)(b1 + 4 * lane);
    float o0 = acc.x / den + bb.x;
    float o1 = acc.y / den + bb.y;
    float o2 = acc.z / den + bb.z;
    float o3 = acc.w / den + bb.w;
    o0 = o0 > 0.f ? o0 : (__expf(o0) - 1.f);
    o1 = o1 > 0.f ? o1 : (__expf(o1) - 1.f);
    o2 = o2 > 0.f ? o2 : (__expf(o2) - 1.f);
    o3 = o3 > 0.f ? o3 : (__expf(o3) - 1.f);
    *(float4*)(g_x2 + (size_t)n * 128 + 4 * lane) = make_float4(o0, o1, o2, o3);
}

// ---------------- GEMM2 + att2 fused ([50000,128] x [128,40]) -----------------
// 64 nodes/block, 320 threads: (cg 0..9 -> float4 of 4 cols, ty 0..31 -> 2 nodes)
__global__ void k_gemm2_att2(const float* __restrict__ W,
                             const float* __restrict__ att_src,
                             const float* __restrict__ att_dst, int N) {
    __shared__ float xs[64][129];
    __shared__ float sAs[64], sAd[64];
    int tid = threadIdx.x;
    int nb = blockIdx.x * 64;
    const float4* xg = (const float4*)g_x2 + (size_t)nb * 32;
    for (int i = tid; i < 64 * 32; i += 320) {
        int r = i >> 5, c4 = (i & 31) * 4;
        float4 v = (nb + r < N) ? xg[i] : make_float4(0.f, 0.f, 0.f, 0.f);
        xs[r][c4] = v.x; xs[r][c4 + 1] = v.y; xs[r][c4 + 2] = v.z; xs[r][c4 + 3] = v.w;
    }
    if (tid < 64) { sAs[tid] = 0.f; sAd[tid] = 0.f; }
    __syncthreads();
    int cg = tid % 10;
    int ty = tid / 10;
    float4 a0 = make_float4(0.f, 0.f, 0.f, 0.f);
    float4 a1 = make_float4(0.f, 0.f, 0.f, 0.f);
    #pragma unroll 4
    for (int k = 0; k < 128; k++) {
        float4 wv = *(const float4*)(W + k * 40 + 4 * cg);
        float x0 = xs[ty][k], x1 = xs[ty + 32][k];
        a0.x += x0 * wv.x; a0.y += x0 * wv.y; a0.z += x0 * wv.z; a0.w += x0 * wv.w;
        a1.x += x1 * wv.x; a1.y += x1 * wv.y; a1.z += x1 * wv.z; a1.w += x1 * wv.w;
    }
    int n0 = nb + ty, n1 = nb + ty + 32;
    if (n0 < N) *(float4*)(g_h2 + (size_t)n0 * 40 + 4 * cg) = a0;
    if (n1 < N) *(float4*)(g_h2 + (size_t)n1 * 40 + 4 * cg) = a1;

    // fused att2 partial dots -> smem reduction over the 10 col-groups
    float4 av = *(const float4*)(att_src + 4 * cg);
    float4 dv = *(const float4*)(att_dst + 4 * cg);
    atomicAdd(&sAs[ty],      a0.x * av.x + a0.y * av.y + a0.z * av.z + a0.w * av.w);
    atomicAdd(&sAd[ty],      a0.x * dv.x + a0.y * dv.y + a0.z * dv.z + a0.w * dv.w);
    atomicAdd(&sAs[ty + 32], a1.x * av.x + a1.y * av.y + a1.z * av.z + a1.w * av.w);
    atomicAdd(&sAd[ty + 32], a1.x * dv.x + a1.y * dv.y + a1.z * dv.z + a1.w * dv.w);
    __syncthreads();
    if (tid < 64 && nb + tid < N) {
        g_as2[nb + tid] = sAs[tid];
        g_ad2[nb + tid] = sAd[tid];
    }
}

// ---------------- aggregation layer 2 (warp per node, 3 srcs/iter) ------------
__global__ void k_agg2(const float* __restrict__ b2, float* __restrict__ out, int N) {
    int warp = (blockIdx.x * blockDim.x + threadIdx.x) >> 5;
    int lane = threadIdx.x & 31;
    if (warp >= N) return;
    int n = warp;
    int s = g_off[n], epn = g_off[n + 1];
    float adn = g_ad2[n];
    int u = lane / 10;
    int v = lane - u * 10;

    float4 acc = make_float4(0.f, 0.f, 0.f, 0.f);
    float den = 0.f;
    for (int j0 = s; j0 < epn; j0 += 32) {
        int j = j0 + lane;
        int sc = 0; float w = 0.f;
        if (j < epn) {
            sc = g_csr[j];
            w = __expf(lrelu(g_as2[sc] + adn));
        }
        den += w;
        int cnt = min(32, epn - j0);
        for (int i = 0; i < cnt; i += 3) {
            int e = i + u;
            int es = min(e, cnt - 1);
            int   ss = __shfl_sync(0xffffffffu, sc, es);
            float ww = __shfl_sync(0xffffffffu, w,  es);
            if (e < cnt && u < 3) {
                float4 hv = *(const float4*)(g_h2 + (size_t)ss * 40 + 4 * v);
                acc.x += ww * hv.x; acc.y += ww * hv.y;
                acc.z += ww * hv.z; acc.w += ww * hv.w;
            }
        }
    }
    den = warp_sum(den) + 1e-16f;
    float4 t1, t2;
    t1.x = __shfl_down_sync(0xffffffffu, acc.x, 10);
    t1.y = __shfl_down_sync(0xffffffffu, acc.y, 10);
    t1.z = __shfl_down_sync(0xffffffffu, acc.z, 10);
    t1.w = __shfl_down_sync(0xffffffffu, acc.w, 10);
    t2.x = __shfl_down_sync(0xffffffffu, acc.x, 20);
    t2.y = __shfl_down_sync(0xffffffffu, acc.y, 20);
    t2.z = __shfl_down_sync(0xffffffffu, acc.z, 20);
    t2.w = __shfl_down_sync(0xffffffffu, acc.w, 20);
    if (lane < 10) {
        float4 bb = *(const float4*)(b2 + 4 * lane);
        float4 o;
        o.x = (acc.x + t1.x + t2.x) / den + bb.x;
        o.y = (acc.y + t1.y + t2.y) / den + bb.y;
        o.z = (acc.z + t1.z + t2.z) / den + bb.z;
        o.w = (acc.w + t1.w + t2.w) / den + bb.w;
        *(float4*)(out + (size_t)n * 40 + 4 * lane) = o;
    }
}

// ---------------- launch ----------------
extern "C" void kernel_launch(void* const* d_in, const int* in_sizes, int n_in,
                              void* d_out, int out_size) {
    const float* node_feat = (const float*)d_in[0];
    const void*  edge_idx  = d_in[1];
    const float* W1        = (const float*)d_in[2];
    const float* att_src1  = (const float*)d_in[3];
    const float* att_dst1  = (const float*)d_in[4];
    const float* b1        = (const float*)d_in[5];
    const float* W2        = (const float*)d_in[6];
    const float* att_src2  = (const float*)d_in[7];
    const float* att_dst2  = (const float*)d_in[8];
    const float* b2        = (const float*)d_in[9];
    float*       out       = (float*)d_out;

    const int N = in_sizes[0] / IN_CH;     // 50000
    const int E = in_sizes[1] / 2;         // 800000
    const int total = E + N;               // 850000

    const int G1B = (N + 31) / 32;         // gemm1 blocks
    const int HB  = (total + 255) / 256;   // hist blocks
    const int A1B = 1 + (N + 31) / 32;     // scan block + att1 blocks
    int warpBlocks = (N * 32 + 255) / 256;

    k_detect    <<<1, 1>>>((const int*)edge_idx, E);
    k_gemm1_hist<<<G1B + HB, 256>>>(node_feat, W1, edge_idx, E, total, N, G1B);
    k_scan_att1 <<<A1B, 1024>>>(att_src1, att_dst1, N);
    k_scatter   <<<HB, 256>>>(edge_idx, E, total, N);
    k_agg1      <<<warpBlocks, 256>>>(b1, N);
    k_gemm2_att2<<<(N + 63) / 64, 320>>>(W2, att_src2, att_dst2, N);
    k_agg2      <<<warpBlocks, 256>>>(b2, out, N);
}

// round 12
// speedup vs baseline: 1.0258x; 1.0258x over previous
#include <cuda_runtime.h>

// ---------------- problem constants ----------------
#define N_NODES 50000
#define E_EDGES 800000
#define TE (E_EDGES + N_NODES)   // edges + self-loops
#define IN_CH   128
#define HID2    128              // HEADS*HIDDEN = 2*64
#define OUT_CH  40
#define NEG_SLOPE 0.2f

// ---------------- scratch (device globals; NEVER touched from host) ----------
__device__ float g_h1[(size_t)N_NODES * HID2];
__device__ float g_x2[(size_t)N_NODES * HID2];
__device__ float g_h2[(size_t)N_NODES * OUT_CH];
__device__ float g_as1[N_NODES * 2];
__device__ float g_ad1[N_NODES * 2];
__device__ float g_as2[N_NODES];
__device__ float g_ad2[N_NODES];
__device__ int   g_deg[N_NODES];   // zero at load; re-zeroed by k_scan each call
__device__ int   g_off[N_NODES + 1];
__device__ int   g_cur[N_NODES];
__device__ int   g_csr[TE];
__device__ int   g_is64;

// ---------------- helpers ----------------
__device__ __forceinline__ float warp_sum(float v) {
    #pragma unroll
    for (int o = 16; o; o >>= 1) v += __shfl_xor_sync(0xffffffffu, v, o);
    return v;
}
__device__ __forceinline__ float lrelu(float x) {
    return x >= 0.f ? x : NEG_SLOPE * x;
}
__device__ __forceinline__ int edge_val(const void* ei, size_t idx) {
    if (g_is64) return (int)((const long long*)ei)[idx];
    return ((const int*)ei)[idx];
}

// ---------------- edge dtype detection (1 thread; replaces zero pass) ---------
__global__ void k_detect(const int* __restrict__ ei32, int E) {
    int nz = 0;
    int stride = E / 64;
    for (int k = 0; k < 64; k++)
        nz |= ei32[2 * (size_t)(k * stride) + 1];
    g_is64 = (nz == 0) ? 1 : 0;
}

// ---------------- CSR build ----------------
__global__ void k_hist(const void* __restrict__ ei, int E, int total, int N) {
    int t = blockIdx.x * blockDim.x + threadIdx.x;
    if (t >= total) return;
    int src, dst;
    if (t < E) { src = edge_val(ei, t); dst = edge_val(ei, (size_t)E + t); }
    else       { src = t - E;           dst = t - E; }
    if ((unsigned)dst >= (unsigned)N || (unsigned)src >= (unsigned)N) return;
    atomicAdd(&g_deg[dst], 1);
}
__global__ void k_scan(int N) {   // single block of 1024; also re-zeroes g_deg
    __shared__ int ssum[1024];
    int t = threadIdx.x;
    int chunk = (N + 1023) / 1024;
    int s = t * chunk;
    int e = min(N, s + chunk);
    int sum = 0;
    for (int i = s; i < e; i++) sum += g_deg[i];
    ssum[t] = sum;
    __syncthreads();
    for (int o = 1; o < 1024; o <<= 1) {
        int v = (t >= o) ? ssum[t - o] : 0;
        __syncthreads();
        ssum[t] += v;
        __syncthreads();
    }
    int run = (t > 0) ? ssum[t - 1] : 0;
    for (int i = s; i < e; i++) {
        int d = g_deg[i];
        g_off[i] = run; g_cur[i] = run;
        g_deg[i] = 0;               // restore state for next call
        run += d;
    }
    if (s < N && e == N) g_off[N] = run;
}
__global__ void k_scatter(const void* __restrict__ ei, int E, int total, int N) {
    int t = blockIdx.x * blockDim.x + threadIdx.x;
    if (t >= total) return;
    int src, dst;
    if (t < E) { src = edge_val(ei, t); dst = edge_val(ei, (size_t)E + t); }
    else       { src = t - E;           dst = t - E; }
    if ((unsigned)dst >= (unsigned)N || (unsigned)src >= (unsigned)N) return;
    int pos = atomicAdd(&g_cur[dst], 1);
    g_csr[pos] = src;
}

// ---------------- GEMM1: g_h1 = x @ W1  ([50000,128] x [128,128]) -------------
// 32 nodes/block, 256 threads. thread = (col2 0..63, rg 0..3): cols {c,c+64},
// rows rg*8..rg*8+7. (measured-best R6 version)
__global__ void k_gemm1(const float* __restrict__ x, const float* __restrict__ W,
                        int N) {
    __shared__ __align__(16) float4 xs4[32][32];   // [row][k/4]
    int nb = blockIdx.x * 32;
    const float4* xg = (const float4*)x + (size_t)nb * 32;
    for (int i = threadIdx.x; i < 32 * 32; i += 256) {
        int r = i >> 5;
        xs4[r][i & 31] = (nb + r < N) ? xg[i] : make_float4(0.f, 0.f, 0.f, 0.f);
    }
    __syncthreads();
    int col = threadIdx.x & 63;
    int rg  = threadIdx.x >> 6;
    float accA[8], accB[8];
    #pragma unroll
    for (int r = 0; r < 8; r++) { accA[r] = 0.f; accB[r] = 0.f; }
    #pragma unroll 2
    for (int k4 = 0; k4 < 32; k4++) {
        const float* Wk = W + 4 * k4 * 128;
        float a0 = Wk[col],            a1 = Wk[128 + col];
        float a2 = Wk[256 + col],      a3 = Wk[384 + col];
        float b0 = Wk[col + 64],       b1 = Wk[128 + col + 64];
        float b2 = Wk[256 + col + 64], b3 = Wk[384 + col + 64];
        #pragma unroll
        for (int r = 0; r < 8; r++) {
            float4 v = xs4[rg * 8 + r][k4];
            accA[r] += v.x * a0 + v.y * a1 + v.z * a2 + v.w * a3;
            accB[r] += v.x * b0 + v.y * b1 + v.z * b2 + v.w * b3;
        }
    }
    #pragma unroll
    for (int r = 0; r < 8; r++) {
        int nn = nb + rg * 8 + r;
        if (nn < N) {
            g_h1[(size_t)nn * 128 + col]      = accA[r];
            g_h1[(size_t)nn * 128 + col + 64] = accB[r];
        }
    }
}

// ---------------- attention dots layer 1 (warp per node, float4) --------------
__global__ void k_att1(const float* __restrict__ att_src,
                       const float* __restrict__ att_dst, int N) {
    int warp = (blockIdx.x * blockDim.x + threadIdx.x) >> 5;
    int lane = threadIdx.x & 31;
    if (warp >= N) return;
    float4 h = *(const float4*)(g_h1 + (size_t)warp * 128 + 4 * lane);
    float4 a = *(const float4*)(att_src + 4 * lane);
    float4 d = *(const float4*)(att_dst + 4 * lane);
    float as = h.x * a.x + h.y * a.y + h.z * a.z + h.w * a.w;
    float ad = h.x * d.x + h.y * d.y + h.z * d.z + h.w * d.w;
    #pragma unroll
    for (int o = 8; o; o >>= 1) {
        as += __shfl_xor_sync(0xffffffffu, as, o);
        ad += __shfl_xor_sync(0xffffffffu, ad, o);
    }
    float as1v = __shfl_sync(0xffffffffu, as, 16);
    float ad1v = __shfl_sync(0xffffffffu, ad, 16);
    if (lane == 0) {
        g_as1[2 * warp] = as; g_as1[2 * warp + 1] = as1v;
        g_ad1[2 * warp] = ad; g_ad1[2 * warp + 1] = ad1v;
    }
}

// ---------------- aggregation layer 1 (warp per node, float4 gather) ----------
__global__ void k_agg1(const float* __restrict__ b1, int N) {
    int warp = (blockIdx.x * blockDim.x + threadIdx.x) >> 5;
    int lane = threadIdx.x & 31;
    if (warp >= N) return;
    int n = warp;
    int s = g_off[n], epn = g_off[n + 1];
    float ad0 = g_ad1[2 * n], ad1 = g_ad1[2 * n + 1];
    const float* hbase = g_h1 + 4 * lane;
    bool head0 = (lane < 16);

    float4 acc = make_float4(0.f, 0.f, 0.f, 0.f);
    float den0 = 0.f, den1 = 0.f;

    for (int j0 = s; j0 < epn; j0 += 32) {
        int j = j0 + lane;
        int sc = 0; float w0 = 0.f, w1 = 0.f;
        if (j < epn) {
            sc = g_csr[j];
            float2 as = *(const float2*)(g_as1 + 2 * sc);
            w0 = __expf(lrelu(as.x + ad0));
            w1 = __expf(lrelu(as.y + ad1));
        }
        den0 += w0; den1 += w1;
        int cnt = min(32, epn - j0);
        int i = 0;
        #define STEP(u) {                                                   \
            int   ss = __shfl_sync(0xffffffffu, sc, i + (u));               \
            float wa = __shfl_sync(0xffffffffu, w0, i + (u));               \
            float wb = __shfl_sync(0xffffffffu, w1, i + (u));               \
            float ww = head0 ? wa : wb;                                     \
            float4 v = *(const float4*)(hbase + (size_t)ss * 128);          \
            acc.x += ww * v.x; acc.y += ww * v.y;                           \
            acc.z += ww * v.z; acc.w += ww * v.w; }
        for (; i + 8 <= cnt; i += 8) {
            STEP(0) STEP(1) STEP(2) STEP(3) STEP(4) STEP(5) STEP(6) STEP(7)
        }
        for (; i < cnt; i++) { STEP(0) }
        #undef STEP
    }
    den0 = warp_sum(den0) + 1e-16f;
    den1 = warp_sum(den1) + 1e-16f;
    float den = head0 ? den0 : den1;

    float4 bb = *(const float4*)(b1 + 4 * lane);
    float o0 = acc.x / den + bb.x;
    float o1 = acc.y / den + bb.y;
    float o2 = acc.z / den + bb.z;
    float o3 = acc.w / den + bb.w;
    o0 = o0 > 0.f ? o0 : (__expf(o0) - 1.f);
    o1 = o1 > 0.f ? o1 : (__expf(o1) - 1.f);
    o2 = o2 > 0.f ? o2 : (__expf(o2) - 1.f);
    o3 = o3 > 0.f ? o3 : (__expf(o3) - 1.f);
    *(float4*)(g_x2 + (size_t)n * 128 + 4 * lane) = make_float4(o0, o1, o2, o3);
}

// ---------------- GEMM2: g_h2 = g_x2 @ W2 ([50000,128] x [128,40]) ------------
__global__ void k_gemm2(const float* __restrict__ W, int N) {
    __shared__ float xs[64][129];
    int nb = blockIdx.x * 64;
    const float4* xg = (const float4*)g_x2 + (size_t)nb * 32;
    for (int i = threadIdx.x; i < 64 * 32; i += 320) {
        int r = i >> 5, c4 = (i & 31) * 4;
        float4 v = (nb + r < N) ? xg[i] : make_float4(0.f, 0.f, 0.f, 0.f);
        xs[r][c4] = v.x; xs[r][c4 + 1] = v.y; xs[r][c4 + 2] = v.z; xs[r][c4 + 3] = v.w;
    }
    __syncthreads();
    int cg = threadIdx.x % 10;
    int ty = threadIdx.x / 10;
    float4 a0 = make_float4(0.f, 0.f, 0.f, 0.f);
    float4 a1 = make_float4(0.f, 0.f, 0.f, 0.f);
    #pragma unroll 4
    for (int k = 0; k < 128; k++) {
        float4 wv = *(const float4*)(W + k * 40 + 4 * cg);
        float x0 = xs[ty][k], x1 = xs[ty + 32][k];
        a0.x += x0 * wv.x; a0.y += x0 * wv.y; a0.z += x0 * wv.z; a0.w += x0 * wv.w;
        a1.x += x1 * wv.x; a1.y += x1 * wv.y; a1.z += x1 * wv.z; a1.w += x1 * wv.w;
    }
    int n0 = nb + ty, n1 = nb + ty + 32;
    if (n0 < N) *(float4*)(g_h2 + (size_t)n0 * 40 + 4 * cg) = a0;
    if (n1 < N) *(float4*)(g_h2 + (size_t)n1 * 40 + 4 * cg) = a1;
}

// ---------------- attention dots layer 2 (warp per node, 40 ch) ---------------
__global__ void k_att2(const float* __restrict__ att_src,
                       const float* __restrict__ att_dst, int N) {
    int warp = (blockIdx.x * blockDim.x + threadIdx.x) >> 5;
    int lane = threadIdx.x & 31;
    if (warp >= N) return;
    float as = 0.f, ad = 0.f;
    if (lane < 10) {
        float4 h = *(const float4*)(g_h2 + (size_t)warp * 40 + 4 * lane);
        float4 a = *(const float4*)(att_src + 4 * lane);
        float4 d = *(const float4*)(att_dst + 4 * lane);
        as = h.x * a.x + h.y * a.y + h.z * a.z + h.w * a.w;
        ad = h.x * d.x + h.y * d.y + h.z * d.z + h.w * d.w;
    }
    as = warp_sum(as); ad = warp_sum(ad);
    if (lane == 0) { g_as2[warp] = as; g_ad2[warp] = ad; }
}

// ---------------- aggregation layer 2 (warp per node, 3 srcs/iter) ------------
__global__ void k_agg2(const float* __restrict__ b2, float* __restrict__ out, int N) {
    int warp = (blockIdx.x * blockDim.x + threadIdx.x) >> 5;
    int lane = threadIdx.x & 31;
    if (warp >= N) return;
    int n = warp;
    int s = g_off[n], epn = g_off[n + 1];
    float adn = g_ad2[n];
    int u = lane / 10;
    int v = lane - u * 10;

    float4 acc = make_float4(0.f, 0.f, 0.f, 0.f);
    float den = 0.f;
    for (int j0 = s; j0 < epn; j0 += 32) {
        int j = j0 + lane;
        int sc = 0; float w = 0.f;
        if (j < epn) {
            sc = g_csr[j];
            w = __expf(lrelu(g_as2[sc] + adn));
        }
        den += w;
        int cnt = min(32, epn - j0);
        for (int i = 0; i < cnt; i += 3) {
            int e = i + u;
            int es = min(e, cnt - 1);
            int   ss = __shfl_sync(0xffffffffu, sc, es);
            float ww = __shfl_sync(0xffffffffu, w,  es);
            if (e < cnt && u < 3) {
                float4 hv = *(const float4*)(g_h2 + (size_t)ss * 40 + 4 * v);
                acc.x += ww * hv.x; acc.y += ww * hv.y;
                acc.z += ww * hv.z; acc.w += ww * hv.w;
            }
        }
    }
    den = warp_sum(den) + 1e-16f;
    float4 t1, t2;
    t1.x = __shfl_down_sync(0xffffffffu, acc.x, 10);
    t1.y = __shfl_down_sync(0xffffffffu, acc.y, 10);
    t1.z = __shfl_down_sync(0xffffffffu, acc.z, 10);
    t1.w = __shfl_down_sync(0xffffffffu, acc.w, 10);
    t2.x = __shfl_down_sync(0xffffffffu, acc.x, 20);
    t2.y = __shfl_down_sync(0xffffffffu, acc.y, 20);
    t2.z = __shfl_down_sync(0xffffffffu, acc.z, 20);
    t2.w = __shfl_down_sync(0xffffffffu, acc.w, 20);
    if (lane < 10) {
        float4 bb = *(const float4*)(b2 + 4 * lane);
        float4 o;
        o.x = (acc.x + t1.x + t2.x) / den + bb.x;
        o.y = (acc.y + t1.y + t2.y) / den + bb.y;
        o.z = (acc.z + t1.z + t2.z) / den + bb.z;
        o.w = (acc.w + t1.w + t2.w) / den + bb.w;
        *(float4*)(out + (size_t)n * 40 + 4 * lane) = o;
    }
}

// ---------------- launch ----------------
extern "C" void kernel_launch(void* const* d_in, const int* in_sizes, int n_in,
                              void* d_out, int out_size) {
    const float* node_feat = (const float*)d_in[0];
    const void*  edge_idx  = d_in[1];
    const float* W1        = (const float*)d_in[2];
    const float* att_src1  = (const float*)d_in[3];
    const float* att_dst1  = (const float*)d_in[4];
    const float* b1        = (const float*)d_in[5];
    const float* W2        = (const float*)d_in[6];
    const float* att_src2  = (const float*)d_in[7];
    const float* att_dst2  = (const float*)d_in[8];
    const float* b2        = (const float*)d_in[9];
    float*       out       = (float*)d_out;

    const int N = in_sizes[0] / IN_CH;     // 50000
    const int E = in_sizes[1] / 2;         // 800000
    const int total = E + N;               // 850000

    int warpBlocks = (N * 32 + 255) / 256;

    k_detect <<<1, 1>>>((const int*)edge_idx, E);
    k_hist   <<<(total + 255) / 256, 256>>>(edge_idx, E, total, N);
    k_scan   <<<1, 1024>>>(N);
    k_scatter<<<(total + 255) / 256, 256>>>(edge_idx, E, total, N);

    k_gemm1<<<(N + 31) / 32, 256>>>(node_feat, W1, N);
    k_att1 <<<warpBlocks, 256>>>(att_src1, att_dst1, N);
    k_agg1 <<<warpBlocks, 256>>>(b1, N);

    k_gemm2<<<(N + 63) / 64, 320>>>(W2, N);
    k_att2 <<<warpBlocks, 256>>>(att_src2, att_dst2, N);
    k_agg2 <<<warpBlocks, 256>>>(b2, out, N);
}

// round 13
// speedup vs baseline: 1.1055x; 1.0777x over previous
#include <cuda_runtime.h>
#include <cuda_fp16.h>

// ---------------- problem constants ----------------
#define N_NODES 50000
#define E_EDGES 800000
#define TE (E_EDGES + N_NODES)   // edges + self-loops
#define IN_CH   128
#define HID2    128              // HEADS*HIDDEN = 2*64
#define OUT_CH  40
#define NEG_SLOPE 0.2f

// ---------------- scratch (device globals; NEVER touched from host) ----------
__device__ __align__(16) __half g_h1[(size_t)N_NODES * HID2];   // fp16 gather table
__device__ float  g_x2[(size_t)N_NODES * HID2];
__device__ __align__(16) __half g_h2[(size_t)N_NODES * OUT_CH]; // fp16 gather table
__device__ float g_as1[N_NODES * 2];
__device__ float g_ad1[N_NODES * 2];
__device__ float g_as2[N_NODES];
__device__ float g_ad2[N_NODES];
__device__ int   g_deg[N_NODES];
__device__ int   g_off[N_NODES + 1];
__device__ int   g_cur[N_NODES];
__device__ int   g_csr[TE];
__device__ int   g_is64;

// ---------------- helpers ----------------
__device__ __forceinline__ float warp_sum(float v) {
    #pragma unroll
    for (int o = 16; o; o >>= 1) v += __shfl_xor_sync(0xffffffffu, v, o);
    return v;
}
__device__ __forceinline__ float lrelu(float x) {
    return x >= 0.f ? x : NEG_SLOPE * x;
}
__device__ __forceinline__ int edge_val(const void* ei, size_t idx) {
    if (g_is64) return (int)((const long long*)ei)[idx];
    return ((const int*)ei)[idx];
}
// load 4 halves (8B) and widen to 4 floats
__device__ __forceinline__ float4 ld_half4(const __half* p) {
    uint2 rv = *(const uint2*)p;
    float2 f01 = __half22float2(*(__half2*)&rv.x);
    float2 f23 = __half22float2(*(__half2*)&rv.y);
    return make_float4(f01.x, f01.y, f23.x, f23.y);
}
// pack 4 floats into 4 halves (8B)
__device__ __forceinline__ uint2 pack_half4(float4 v) {
    __half2 p0 = __float22half2_rn(make_float2(v.x, v.y));
    __half2 p1 = __float22half2_rn(make_float2(v.z, v.w));
    uint2 r;
    r.x = *(unsigned*)&p0;
    r.y = *(unsigned*)&p1;
    return r;
}

// ---------------- zero degrees + detect edge dtype (294.9-build structure) ----
__global__ void k_zero_detect(const int* __restrict__ ei32, int E, int N) {
    int i = blockIdx.x * blockDim.x + threadIdx.x;
    if (i < N) g_deg[i] = 0;
    if (i == 0) {
        int nz = 0;
        int stride = E / 64;
        for (int k = 0; k < 64; k++)
            nz |= ei32[2 * (size_t)(k * stride) + 1];
        g_is64 = (nz == 0) ? 1 : 0;
    }
}

// ---------------- CSR build ----------------
__global__ void k_hist(const void* __restrict__ ei, int E, int total, int N) {
    int t = blockIdx.x * blockDim.x + threadIdx.x;
    if (t >= total) return;
    int src, dst;
    if (t < E) { src = edge_val(ei, t); dst = edge_val(ei, (size_t)E + t); }
    else       { src = t - E;           dst = t - E; }
    if ((unsigned)dst >= (unsigned)N || (unsigned)src >= (unsigned)N) return;
    atomicAdd(&g_deg[dst], 1);
}
__global__ void k_scan(int N) {   // single block of 1024
    __shared__ int ssum[1024];
    int t = threadIdx.x;
    int chunk = (N + 1023) / 1024;
    int s = t * chunk;
    int e = min(N, s + chunk);
    int sum = 0;
    for (int i = s; i < e; i++) sum += g_deg[i];
    ssum[t] = sum;
    __syncthreads();
    for (int o = 1; o < 1024; o <<= 1) {
        int v = (t >= o) ? ssum[t - o] : 0;
        __syncthreads();
        ssum[t] += v;
        __syncthreads();
    }
    int run = (t > 0) ? ssum[t - 1] : 0;
    for (int i = s; i < e; i++) {
        g_off[i] = run; g_cur[i] = run;
        run += g_deg[i];
    }
    if (s < N && e == N) g_off[N] = run;
}
__global__ void k_scatter(const void* __restrict__ ei, int E, int total, int N) {
    int t = blockIdx.x * blockDim.x + threadIdx.x;
    if (t >= total) return;
    int src, dst;
    if (t < E) { src = edge_val(ei, t); dst = edge_val(ei, (size_t)E + t); }
    else       { src = t - E;           dst = t - E; }
    if ((unsigned)dst >= (unsigned)N || (unsigned)src >= (unsigned)N) return;
    int pos = atomicAdd(&g_cur[dst], 1);
    g_csr[pos] = src;
}

// ---------------- GEMM1: g_h1 = x @ W1  ([50000,128] x [128,128], fp16 out) ---
// 32 nodes/block, 256 threads. thread = (col2 0..63, rg 0..3): cols {c,c+64},
// rows rg*8..rg*8+7.  (294.9-measured mainloop; only stores changed to fp16)
__global__ void k_gemm1(const float* __restrict__ x, const float* __restrict__ W,
                        int N) {
    __shared__ __align__(16) float4 xs4[32][32];   // [row][k/4]
    int nb = blockIdx.x * 32;
    const float4* xg = (const float4*)x + (size_t)nb * 32;
    for (int i = threadIdx.x; i < 32 * 32; i += 256) {
        int r = i >> 5;
        xs4[r][i & 31] = (nb + r < N) ? xg[i] : make_float4(0.f, 0.f, 0.f, 0.f);
    }
    __syncthreads();
    int col = threadIdx.x & 63;
    int rg  = threadIdx.x >> 6;
    float accA[8], accB[8];
    #pragma unroll
    for (int r = 0; r < 8; r++) { accA[r] = 0.f; accB[r] = 0.f; }
    #pragma unroll 2
    for (int k4 = 0; k4 < 32; k4++) {
        const float* Wk = W + 4 * k4 * 128;
        float a0 = Wk[col],            a1 = Wk[128 + col];
        float a2 = Wk[256 + col],      a3 = Wk[384 + col];
        float b0 = Wk[col + 64],       b1 = Wk[128 + col + 64];
        float b2 = Wk[256 + col + 64], b3 = Wk[384 + col + 64];
        #pragma unroll
        for (int r = 0; r < 8; r++) {
            float4 v = xs4[rg * 8 + r][k4];
            accA[r] += v.x * a0 + v.y * a1 + v.z * a2 + v.w * a3;
            accB[r] += v.x * b0 + v.y * b1 + v.z * b2 + v.w * b3;
        }
    }
    #pragma unroll
    for (int r = 0; r < 8; r++) {
        int nn = nb + rg * 8 + r;
        if (nn < N) {
            g_h1[(size_t)nn * 128 + col]      = __float2half_rn(accA[r]);
            g_h1[(size_t)nn * 128 + col + 64] = __float2half_rn(accB[r]);
        }
    }
}

// ---------------- attention dots layer 1 (warp per node, fp16 reads) ----------
__global__ void k_att1(const float* __restrict__ att_src,
                       const float* __restrict__ att_dst, int N) {
    int warp = (blockIdx.x * blockDim.x + threadIdx.x) >> 5;
    int lane = threadIdx.x & 31;
    if (warp >= N) return;
    float4 h = ld_half4(g_h1 + (size_t)warp * 128 + 4 * lane);
    float4 a = *(const float4*)(att_src + 4 * lane);
    float4 d = *(const float4*)(att_dst + 4 * lane);
    float as = h.x * a.x + h.y * a.y + h.z * a.z + h.w * a.w;
    float ad = h.x * d.x + h.y * d.y + h.z * d.z + h.w * d.w;
    #pragma unroll
    for (int o = 8; o; o >>= 1) {
        as += __shfl_xor_sync(0xffffffffu, as, o);
        ad += __shfl_xor_sync(0xffffffffu, ad, o);
    }
    float as1v = __shfl_sync(0xffffffffu, as, 16);
    float ad1v = __shfl_sync(0xffffffffu, ad, 16);
    if (lane == 0) {
        g_as1[2 * warp] = as; g_as1[2 * warp + 1] = as1v;
        g_ad1[2 * warp] = ad; g_ad1[2 * warp + 1] = ad1v;
    }
}

// ---------------- aggregation layer 1 (warp per node, fp16 gather) ------------
__global__ void k_agg1(const float* __restrict__ b1, int N) {
    int warp = (blockIdx.x * blockDim.x + threadIdx.x) >> 5;
    int lane = threadIdx.x & 31;
    if (warp >= N) return;
    int n = warp;
    int s = g_off[n], epn = g_off[n + 1];
    float ad0 = g_ad1[2 * n], ad1 = g_ad1[2 * n + 1];
    bool head0 = (lane < 16);

    float4 acc = make_float4(0.f, 0.f, 0.f, 0.f);
    float den0 = 0.f, den1 = 0.f;

    for (int j0 = s; j0 < epn; j0 += 32) {
        int j = j0 + lane;
        int sc = 0; float w0 = 0.f, w1 = 0.f;
        if (j < epn) {
            sc = g_csr[j];
            float2 as = *(const float2*)(g_as1 + 2 * sc);
            w0 = __expf(lrelu(as.x + ad0));
            w1 = __expf(lrelu(as.y + ad1));
        }
        den0 += w0; den1 += w1;
        int cnt = min(32, epn - j0);
        int i = 0;
        #define STEP(u) {                                                   \
            int   ss = __shfl_sync(0xffffffffu, sc, i + (u));               \
            float wa = __shfl_sync(0xffffffffu, w0, i + (u));               \
            float wb = __shfl_sync(0xffffffffu, w1, i + (u));               \
            float ww = head0 ? wa : wb;                                     \
            float4 v = ld_half4(g_h1 + (size_t)ss * 128 + 4 * lane);        \
            acc.x += ww * v.x; acc.y += ww * v.y;                           \
            acc.z += ww * v.z; acc.w += ww * v.w; }
        for (; i + 8 <= cnt; i += 8) {
            STEP(0) STEP(1) STEP(2) STEP(3) STEP(4) STEP(5) STEP(6) STEP(7)
        }
        for (; i < cnt; i++) { STEP(0) }
        #undef STEP
    }
    den0 = warp_sum(den0) + 1e-16f;
    den1 = warp_sum(den1) + 1e-16f;
    float den = head0 ? den0 : den1;

    float4 bb = *(const float4*)(b1 + 4 * lane);
    float o0 = acc.x / den + bb.x;
    float o1 = acc.y / den + bb.y;
    float o2 = acc.z / den + bb.z;
    float o3 = acc.w / den + bb.w;
    o0 = o0 > 0.f ? o0 : (__expf(o0) - 1.f);
    o1 = o1 > 0.f ? o1 : (__expf(o1) - 1.f);
    o2 = o2 > 0.f ? o2 : (__expf(o2) - 1.f);
    o3 = o3 > 0.f ? o3 : (__expf(o3) - 1.f);
    *(float4*)(g_x2 + (size_t)n * 128 + 4 * lane) = make_float4(o0, o1, o2, o3);
}

// ---------------- GEMM2: g_h2 = g_x2 @ W2 ([50000,128] x [128,40], fp16 out) --
__global__ void k_gemm2(const float* __restrict__ W, int N) {
    __shared__ float xs[64][129];
    int nb = blockIdx.x * 64;
    const float4* xg = (const float4*)g_x2 + (size_t)nb * 32;
    for (int i = threadIdx.x; i < 64 * 32; i += 320) {
        int r = i >> 5, c4 = (i & 31) * 4;
        float4 v = (nb + r < N) ? xg[i] : make_float4(0.f, 0.f, 0.f, 0.f);
        xs[r][c4] = v.x; xs[r][c4 + 1] = v.y; xs[r][c4 + 2] = v.z; xs[r][c4 + 3] = v.w;
    }
    __syncthreads();
    int cg = threadIdx.x % 10;
    int ty = threadIdx.x / 10;
    float4 a0 = make_float4(0.f, 0.f, 0.f, 0.f);
    float4 a1 = make_float4(0.f, 0.f, 0.f, 0.f);
    #pragma unroll 4
    for (int k = 0; k < 128; k++) {
        float4 wv = *(const float4*)(W + k * 40 + 4 * cg);
        float x0 = xs[ty][k], x1 = xs[ty + 32][k];
        a0.x += x0 * wv.x; a0.y += x0 * wv.y; a0.z += x0 * wv.z; a0.w += x0 * wv.w;
        a1.x += x1 * wv.x; a1.y += x1 * wv.y; a1.z += x1 * wv.z; a1.w += x1 * wv.w;
    }
    int n0 = nb + ty, n1 = nb + ty + 32;
    if (n0 < N) *(uint2*)(g_h2 + (size_t)n0 * 40 + 4 * cg) = pack_half4(a0);
    if (n1 < N) *(uint2*)(g_h2 + (size_t)n1 * 40 + 4 * cg) = pack_half4(a1);
}

// ---------------- attention dots layer 2 (warp per node, fp16 reads) ----------
__global__ void k_att2(const float* __restrict__ att_src,
                       const float* __restrict__ att_dst, int N) {
    int warp = (blockIdx.x * blockDim.x + threadIdx.x) >> 5;
    int lane = threadIdx.x & 31;
    if (warp >= N) return;
    float as = 0.f, ad = 0.f;
    if (lane < 10) {
        float4 h = ld_half4(g_h2 + (size_t)warp * 40 + 4 * lane);
        float4 a = *(const float4*)(att_src + 4 * lane);
        float4 d = *(const float4*)(att_dst + 4 * lane);
        as = h.x * a.x + h.y * a.y + h.z * a.z + h.w * a.w;
        ad = h.x * d.x + h.y * d.y + h.z * d.z + h.w * d.w;
    }
    as = warp_sum(as); ad = warp_sum(ad);
    if (lane == 0) { g_as2[warp] = as; g_ad2[warp] = ad; }
}

// ---------------- aggregation layer 2 (warp per node, fp16 gather) ------------
__global__ void k_agg2(const float* __restrict__ b2, float* __restrict__ out, int N) {
    int warp = (blockIdx.x * blockDim.x + threadIdx.x) >> 5;
    int lane = threadIdx.x & 31;
    if (warp >= N) return;
    int n = warp;
    int s = g_off[n], epn = g_off[n + 1];
    float adn = g_ad2[n];
    int u = lane / 10;        // src slot 0..2 (u==3: lanes 30,31 inactive)
    int v = lane - u * 10;    // half4 chunk 0..9

    float4 acc = make_float4(0.f, 0.f, 0.f, 0.f);
    float den = 0.f;
    for (int j0 = s; j0 < epn; j0 += 32) {
        int j = j0 + lane;
        int sc = 0; float w = 0.f;
        if (j < epn) {
            sc = g_csr[j];
            w = __expf(lrelu(g_as2[sc] + adn));
        }
        den += w;
        int cnt = min(32, epn - j0);
        for (int i = 0; i < cnt; i += 3) {
            int e = i + u;
            int es = min(e, cnt - 1);
            int   ss = __shfl_sync(0xffffffffu, sc, es);
            float ww = __shfl_sync(0xffffffffu, w,  es);
            if (e < cnt && u < 3) {
                float4 hv = ld_half4(g_h2 + (size_t)ss * 40 + 4 * v);
                acc.x += ww * hv.x; acc.y += ww * hv.y;
                acc.z += ww * hv.z; acc.w += ww * hv.w;
            }
        }
    }
    den = warp_sum(den) + 1e-16f;
    float4 t1, t2;
    t1.x = __shfl_down_sync(0xffffffffu, acc.x, 10);
    t1.y = __shfl_down_sync(0xffffffffu, acc.y, 10);
    t1.z = __shfl_down_sync(0xffffffffu, acc.z, 10);
    t1.w = __shfl_down_sync(0xffffffffu, acc.w, 10);
    t2.x = __shfl_down_sync(0xffffffffu, acc.x, 20);
    t2.y = __shfl_down_sync(0xffffffffu, acc.y, 20);
    t2.z = __shfl_down_sync(0xffffffffu, acc.z, 20);
    t2.w = __shfl_down_sync(0xffffffffu, acc.w, 20);
    if (lane < 10) {
        float4 bb = *(const float4*)(b2 + 4 * lane);
        float4 o;
        o.x = (acc.x + t1.x + t2.x) / den + bb.x;
        o.y = (acc.y + t1.y + t2.y) / den + bb.y;
        o.z = (acc.z + t1.z + t2.z) / den + bb.z;
        o.w = (acc.w + t1.w + t2.w) / den + bb.w;
        *(float4*)(out + (size_t)n * 40 + 4 * lane) = o;
    }
}

// ---------------- launch (294.9-build structure) ----------------
extern "C" void kernel_launch(void* const* d_in, const int* in_sizes, int n_in,
                              void* d_out, int out_size) {
    const float* node_feat = (const float*)d_in[0];
    const void*  edge_idx  = d_in[1];
    const float* W1        = (const float*)d_in[2];
    const float* att_src1  = (const float*)d_in[3];
    const float* att_dst1  = (const float*)d_in[4];
    const float* b1        = (const float*)d_in[5];
    const float* W2        = (const float*)d_in[6];
    const float* att_src2  = (const float*)d_in[7];
    const float* att_dst2  = (const float*)d_in[8];
    const float* b2        = (const float*)d_in[9];
    float*       out       = (float*)d_out;

    const int N = in_sizes[0] / IN_CH;     // 50000
    const int E = in_sizes[1] / 2;         // 800000
    const int total = E + N;               // 850000

    int warpBlocks = (N * 32 + 255) / 256;

    k_zero_detect<<<(N + 255) / 256, 256>>>((const int*)edge_idx, E, N);
    k_hist   <<<(total + 255) / 256, 256>>>(edge_idx, E, total, N);
    k_scan   <<<1, 1024>>>(N);
    k_scatter<<<(total + 255) / 256, 256>>>(edge_idx, E, total, N);

    k_gemm1<<<(N + 31) / 32, 256>>>(node_feat, W1, N);
    k_att1 <<<warpBlocks, 256>>>(att_src1, att_dst1, N);
    k_agg1 <<<warpBlocks, 256>>>(b1, N);

    k_gemm2<<<(N + 63) / 64, 320>>>(W2, N);
    k_att2 <<<warpBlocks, 256>>>(att_src2, att_dst2, N);
    k_agg2 <<<warpBlocks, 256>>>(b2, out, N);
}

// round 14
// speedup vs baseline: 1.2399x; 1.1216x over previous
#include <cuda_runtime.h>
#include <cuda_fp16.h>
#include <mma.h>
using namespace nvcuda;

// ---------------- problem constants ----------------
#define N_NODES 50000
#define E_EDGES 800000
#define TE (E_EDGES + N_NODES)   // edges + self-loops
#define IN_CH   128
#define HID2    128              // HEADS*HIDDEN = 2*64
#define OUT_CH  40
#define NEG_SLOPE 0.2f

// gemm1 wmma smem layout (bytes)
#define WS_LD   136              // halves per W row (16B-pad)
#define XS_LD   136              // halves per x row
#define OUT_LD  132              // floats per out row
#define WS_BYTES (128 * WS_LD * 2)               // 34816
#define XS_BYTES (64 * XS_LD * 2)                // 17408
#define G1_SMEM  (WS_BYTES + XS_BYTES)           // 52224

// ---------------- scratch (device globals; NEVER touched from host) ----------
__device__ __align__(16) __half g_h1[(size_t)N_NODES * HID2];   // fp16 gather table
__device__ float  g_x2[(size_t)N_NODES * HID2];
__device__ __align__(16) __half g_h2[(size_t)N_NODES * OUT_CH]; // fp16 gather table
__device__ float g_as1[N_NODES * 2];
__device__ float g_ad1[N_NODES * 2];
__device__ float g_as2[N_NODES];
__device__ float g_ad2[N_NODES];
__device__ int   g_deg[N_NODES];
__device__ int   g_off[N_NODES + 1];
__device__ int   g_cur[N_NODES];
__device__ int   g_csr[TE];
__device__ int   g_is64;

// ---------------- helpers ----------------
__device__ __forceinline__ float warp_sum(float v) {
    #pragma unroll
    for (int o = 16; o; o >>= 1) v += __shfl_xor_sync(0xffffffffu, v, o);
    return v;
}
__device__ __forceinline__ float lrelu(float x) {
    return x >= 0.f ? x : NEG_SLOPE * x;
}
__device__ __forceinline__ int edge_val(const void* ei, size_t idx) {
    if (g_is64) return (int)((const long long*)ei)[idx];
    return ((const int*)ei)[idx];
}
__device__ __forceinline__ float4 ld_half4(const __half* p) {
    uint2 rv = *(const uint2*)p;
    float2 f01 = __half22float2(*(__half2*)&rv.x);
    float2 f23 = __half22float2(*(__half2*)&rv.y);
    return make_float4(f01.x, f01.y, f23.x, f23.y);
}
__device__ __forceinline__ uint2 pack_half4(float4 v) {
    __half2 p0 = __float22half2_rn(make_float2(v.x, v.y));
    __half2 p1 = __float22half2_rn(make_float2(v.z, v.w));
    uint2 r;
    r.x = *(unsigned*)&p0;
    r.y = *(unsigned*)&p1;
    return r;
}

// ---------------- zero degrees + detect edge dtype ----------------
__global__ void k_zero_detect(const int* __restrict__ ei32, int E, int N) {
    int i = blockIdx.x * blockDim.x + threadIdx.x;
    if (i < N) g_deg[i] = 0;
    if (i == 0) {
        int nz = 0;
        int stride = E / 64;
        for (int k = 0; k < 64; k++)
            nz |= ei32[2 * (size_t)(k * stride) + 1];
        g_is64 = (nz == 0) ? 1 : 0;
    }
}

// ---------------- CSR build ----------------
__global__ void k_hist(const void* __restrict__ ei, int E, int total, int N) {
    int t = blockIdx.x * blockDim.x + threadIdx.x;
    if (t >= total) return;
    int src, dst;
    if (t < E) { src = edge_val(ei, t); dst = edge_val(ei, (size_t)E + t); }
    else       { src = t - E;           dst = t - E; }
    if ((unsigned)dst >= (unsigned)N || (unsigned)src >= (unsigned)N) return;
    atomicAdd(&g_deg[dst], 1);
}
__global__ void k_scan(int N) {   // single block of 1024
    __shared__ int ssum[1024];
    int t = threadIdx.x;
    int chunk = (N + 1023) / 1024;
    int s = t * chunk;
    int e = min(N, s + chunk);
    int sum = 0;
    for (int i = s; i < e; i++) sum += g_deg[i];
    ssum[t] = sum;
    __syncthreads();
    for (int o = 1; o < 1024; o <<= 1) {
        int v = (t >= o) ? ssum[t - o] : 0;
        __syncthreads();
        ssum[t] += v;
        __syncthreads();
    }
    int run = (t > 0) ? ssum[t - 1] : 0;
    for (int i = s; i < e; i++) {
        g_off[i] = run; g_cur[i] = run;
        run += g_deg[i];
    }
    if (s < N && e == N) g_off[N] = run;
}
__global__ void k_scatter(const void* __restrict__ ei, int E, int total, int N) {
    int t = blockIdx.x * blockDim.x + threadIdx.x;
    if (t >= total) return;
    int src, dst;
    if (t < E) { src = edge_val(ei, t); dst = edge_val(ei, (size_t)E + t); }
    else       { src = t - E;           dst = t - E; }
    if ((unsigned)dst >= (unsigned)N || (unsigned)src >= (unsigned)N) return;
    int pos = atomicAdd(&g_cur[dst], 1);
    g_csr[pos] = src;
}

// ---------------- GEMM1 (tensor cores): g_h1 = fp16(x) @ fp16(W1), fp32 accum -
// 64 rows x 128 cols per block, 256 threads = 8 warps in 4x2 grid.
// Warp (wr, wc): rows wr*16..+15, cols wc*64..+63 as 4 m16n16k16 fragments.
__global__ void k_gemm1(const float* __restrict__ x, const float* __restrict__ W,
                        int N) {
    extern __shared__ char smraw[];
    __half* Ws   = (__half*)smraw;                 // [128][WS_LD]
    __half* xs   = (__half*)(smraw + WS_BYTES);    // [64][XS_LD]
    float*  outf = (float*)smraw;                  // [64][OUT_LD] epilogue alias

    int tid = threadIdx.x;
    int nb = blockIdx.x * 64;

    // W fp32 -> fp16 smem (coalesced float4 reads)
    const float4* Wf4 = (const float4*)W;
    for (int i = tid; i < 128 * 32; i += 256) {
        int r = i >> 5, c = (i & 31) * 4;
        float4 v = Wf4[i];
        __half2* p = (__half2*)(Ws + r * WS_LD + c);
        p[0] = __float22half2_rn(make_float2(v.x, v.y));
        p[1] = __float22half2_rn(make_float2(v.z, v.w));
    }
    // x tile fp32 -> fp16 smem
    for (int i = tid; i < 64 * 32; i += 256) {
        int r = i >> 5, c = (i & 31) * 4;
        float4 v = (nb + r < N) ? *(const float4*)(x + (size_t)(nb + r) * 128 + c)
                                : make_float4(0.f, 0.f, 0.f, 0.f);
        __half2* p = (__half2*)(xs + r * XS_LD + c);
        p[0] = __float22half2_rn(make_float2(v.x, v.y));
        p[1] = __float22half2_rn(make_float2(v.z, v.w));
    }
    __syncthreads();

    int wid = tid >> 5;
    int wr = wid >> 1;        // 0..3
    int wc = wid & 1;         // 0..1

    wmma::fragment<wmma::accumulator, 16, 16, 16, float> acc[4];
    #pragma unroll
    for (int f = 0; f < 4; f++) wmma::fill_fragment(acc[f], 0.f);

    #pragma unroll
    for (int k = 0; k < 8; k++) {
        wmma::fragment<wmma::matrix_a, 16, 16, 16, __half, wmma::row_major> a;
        wmma::load_matrix_sync(a, xs + (wr * 16) * XS_LD + k * 16, XS_LD);
        #pragma unroll
        for (int f = 0; f < 4; f++) {
            wmma::fragment<wmma::matrix_b, 16, 16, 16, __half, wmma::row_major> b;
            wmma::load_matrix_sync(b, Ws + (k * 16) * WS_LD + wc * 64 + f * 16, WS_LD);
            wmma::mma_sync(acc[f], a, b, acc[f]);
        }
    }
    __syncthreads();   // done reading Ws/xs; alias as outf

    #pragma unroll
    for (int f = 0; f < 4; f++)
        wmma::store_matrix_sync(outf + (wr * 16) * OUT_LD + wc * 64 + f * 16,
                                acc[f], OUT_LD, wmma::mem_row_major);
    __syncthreads();

    // fp32 smem -> fp16 global (coalesced 8B stores, bounds-guarded)
    for (int i = tid; i < 64 * 32; i += 256) {
        int r = i >> 5, c = (i & 31) * 4;
        if (nb + r < N) {
            float4 v = *(const float4*)(outf + r * OUT_LD + c);
            *(uint2*)(g_h1 + (size_t)(nb + r) * 128 + c) = pack_half4(v);
        }
    }
}

// ---------------- attention dots layer 1 (warp per node, fp16 reads) ----------
__global__ void k_att1(const float* __restrict__ att_src,
                       const float* __restrict__ att_dst, int N) {
    int warp = (blockIdx.x * blockDim.x + threadIdx.x) >> 5;
    int lane = threadIdx.x & 31;
    if (warp >= N) return;
    float4 h = ld_half4(g_h1 + (size_t)warp * 128 + 4 * lane);
    float4 a = *(const float4*)(att_src + 4 * lane);
    float4 d = *(const float4*)(att_dst + 4 * lane);
    float as = h.x * a.x + h.y * a.y + h.z * a.z + h.w * a.w;
    float ad = h.x * d.x + h.y * d.y + h.z * d.z + h.w * d.w;
    #pragma unroll
    for (int o = 8; o; o >>= 1) {
        as += __shfl_xor_sync(0xffffffffu, as, o);
        ad += __shfl_xor_sync(0xffffffffu, ad, o);
    }
    float as1v = __shfl_sync(0xffffffffu, as, 16);
    float ad1v = __shfl_sync(0xffffffffu, ad, 16);
    if (lane == 0) {
        g_as1[2 * warp] = as; g_as1[2 * warp + 1] = as1v;
        g_ad1[2 * warp] = ad; g_ad1[2 * warp + 1] = ad1v;
    }
}

// ---------------- aggregation layer 1 (warp per node, fp16 gather) ------------
__global__ void k_agg1(const float* __restrict__ b1, int N) {
    int warp = (blockIdx.x * blockDim.x + threadIdx.x) >> 5;
    int lane = threadIdx.x & 31;
    if (warp >= N) return;
    int n = warp;
    int s = g_off[n], epn = g_off[n + 1];
    float ad0 = g_ad1[2 * n], ad1 = g_ad1[2 * n + 1];
    bool head0 = (lane < 16);

    float4 acc = make_float4(0.f, 0.f, 0.f, 0.f);
    float den0 = 0.f, den1 = 0.f;

    for (int j0 = s; j0 < epn; j0 += 32) {
        int j = j0 + lane;
        int sc = 0; float w0 = 0.f, w1 = 0.f;
        if (j < epn) {
            sc = g_csr[j];
            float2 as = *(const float2*)(g_as1 + 2 * sc);
            w0 = __expf(lrelu(as.x + ad0));
            w1 = __expf(lrelu(as.y + ad1));
        }
        den0 += w0; den1 += w1;
        int cnt = min(32, epn - j0);
        int i = 0;
        #define STEP(u) {                                                   \
            int   ss = __shfl_sync(0xffffffffu, sc, i + (u));               \
            float wa = __shfl_sync(0xffffffffu, w0, i + (u));               \
            float wb = __shfl_sync(0xffffffffu, w1, i + (u));               \
            float ww = head0 ? wa : wb;                                     \
            float4 v = ld_half4(g_h1 + (size_t)ss * 128 + 4 * lane);        \
            acc.x += ww * v.x; acc.y += ww * v.y;                           \
            acc.z += ww * v.z; acc.w += ww * v.w; }
        for (; i + 8 <= cnt; i += 8) {
            STEP(0) STEP(1) STEP(2) STEP(3) STEP(4) STEP(5) STEP(6) STEP(7)
        }
        for (; i < cnt; i++) { STEP(0) }
        #undef STEP
    }
    den0 = warp_sum(den0) + 1e-16f;
    den1 = warp_sum(den1) + 1e-16f;
    float den = head0 ? den0 : den1;

    float4 bb = *(const float4*)(b1 + 4 * lane);
    float o0 = acc.x / den + bb.x;
    float o1 = acc.y / den + bb.y;
    float o2 = acc.z / den + bb.z;
    float o3 = acc.w / den + bb.w;
    o0 = o0 > 0.f ? o0 : (__expf(o0) - 1.f);
    o1 = o1 > 0.f ? o1 : (__expf(o1) - 1.f);
    o2 = o2 > 0.f ? o2 : (__expf(o2) - 1.f);
    o3 = o3 > 0.f ? o3 : (__expf(o3) - 1.f);
    *(float4*)(g_x2 + (size_t)n * 128 + 4 * lane) = make_float4(o0, o1, o2, o3);
}

// ---------------- GEMM2: g_h2 = g_x2 @ W2 ([50000,128] x [128,40], fp16 out) --
__global__ void k_gemm2(const float* __restrict__ W, int N) {
    __shared__ float xs[64][129];
    int nb = blockIdx.x * 64;
    const float4* xg = (const float4*)g_x2 + (size_t)nb * 32;
    for (int i = threadIdx.x; i < 64 * 32; i += 320) {
        int r = i >> 5, c4 = (i & 31) * 4;
        float4 v = (nb + r < N) ? xg[i] : make_float4(0.f, 0.f, 0.f, 0.f);
        xs[r][c4] = v.x; xs[r][c4 + 1] = v.y; xs[r][c4 + 2] = v.z; xs[r][c4 + 3] = v.w;
    }
    __syncthreads();
    int cg = threadIdx.x % 10;
    int ty = threadIdx.x / 10;
    float4 a0 = make_float4(0.f, 0.f, 0.f, 0.f);
    float4 a1 = make_float4(0.f, 0.f, 0.f, 0.f);
    #pragma unroll 4
    for (int k = 0; k < 128; k++) {
        float4 wv = *(const float4*)(W + k * 40 + 4 * cg);
        float x0 = xs[ty][k], x1 = xs[ty + 32][k];
        a0.x += x0 * wv.x; a0.y += x0 * wv.y; a0.z += x0 * wv.z; a0.w += x0 * wv.w;
        a1.x += x1 * wv.x; a1.y += x1 * wv.y; a1.z += x1 * wv.z; a1.w += x1 * wv.w;
    }
    int n0 = nb + ty, n1 = nb + ty + 32;
    if (n0 < N) *(uint2*)(g_h2 + (size_t)n0 * 40 + 4 * cg) = pack_half4(a0);
    if (n1 < N) *(uint2*)(g_h2 + (size_t)n1 * 40 + 4 * cg) = pack_half4(a1);
}

// ---------------- attention dots layer 2 (warp per node, fp16 reads) ----------
__global__ void k_att2(const float* __restrict__ att_src,
                       const float* __restrict__ att_dst, int N) {
    int warp = (blockIdx.x * blockDim.x + threadIdx.x) >> 5;
    int lane = threadIdx.x & 31;
    if (warp >= N) return;
    float as = 0.f, ad = 0.f;
    if (lane < 10) {
        float4 h = ld_half4(g_h2 + (size_t)warp * 40 + 4 * lane);
        float4 a = *(const float4*)(att_src + 4 * lane);
        float4 d = *(const float4*)(att_dst + 4 * lane);
        as = h.x * a.x + h.y * a.y + h.z * a.z + h.w * a.w;
        ad = h.x * d.x + h.y * d.y + h.z * d.z + h.w * d.w;
    }
    as = warp_sum(as); ad = warp_sum(ad);
    if (lane == 0) { g_as2[warp] = as; g_ad2[warp] = ad; }
}

// ---------------- aggregation layer 2 (warp per node, fp16 gather) ------------
__global__ void k_agg2(const float* __restrict__ b2, float* __restrict__ out, int N) {
    int warp = (blockIdx.x * blockDim.x + threadIdx.x) >> 5;
    int lane = threadIdx.x & 31;
    if (warp >= N) return;
    int n = warp;
    int s = g_off[n], epn = g_off[n + 1];
    float adn = g_ad2[n];
    int u = lane / 10;        // src slot 0..2 (u==3: lanes 30,31 inactive)
    int v = lane - u * 10;    // half4 chunk 0..9

    float4 acc = make_float4(0.f, 0.f, 0.f, 0.f);
    float den = 0.f;
    for (int j0 = s; j0 < epn; j0 += 32) {
        int j = j0 + lane;
        int sc = 0; float w = 0.f;
        if (j < epn) {
            sc = g_csr[j];
            w = __expf(lrelu(g_as2[sc] + adn));
        }
        den += w;
        int cnt = min(32, epn - j0);
        for (int i = 0; i < cnt; i += 3) {
            int e = i + u;
            int es = min(e, cnt - 1);
            int   ss = __shfl_sync(0xffffffffu, sc, es);
            float ww = __shfl_sync(0xffffffffu, w,  es);
            if (e < cnt && u < 3) {
                float4 hv = ld_half4(g_h2 + (size_t)ss * 40 + 4 * v);
                acc.x += ww * hv.x; acc.y += ww * hv.y;
                acc.z += ww * hv.z; acc.w += ww * hv.w;
            }
        }
    }
    den = warp_sum(den) + 1e-16f;
    float4 t1, t2;
    t1.x = __shfl_down_sync(0xffffffffu, acc.x, 10);
    t1.y = __shfl_down_sync(0xffffffffu, acc.y, 10);
    t1.z = __shfl_down_sync(0xffffffffu, acc.z, 10);
    t1.w = __shfl_down_sync(0xffffffffu, acc.w, 10);
    t2.x = __shfl_down_sync(0xffffffffu, acc.x, 20);
    t2.y = __shfl_down_sync(0xffffffffu, acc.y, 20);
    t2.z = __shfl_down_sync(0xffffffffu, acc.z, 20);
    t2.w = __shfl_down_sync(0xffffffffu, acc.w, 20);
    if (lane < 10) {
        float4 bb = *(const float4*)(b2 + 4 * lane);
        float4 o;
        o.x = (acc.x + t1.x + t2.x) / den + bb.x;
        o.y = (acc.y + t1.y + t2.y) / den + bb.y;
        o.z = (acc.z + t1.z + t2.z) / den + bb.z;
        o.w = (acc.w + t1.w + t2.w) / den + bb.w;
        *(float4*)(out + (size_t)n * 40 + 4 * lane) = o;
    }
}

// ---------------- launch ----------------
extern "C" void kernel_launch(void* const* d_in, const int* in_sizes, int n_in,
                              void* d_out, int out_size) {
    const float* node_feat = (const float*)d_in[0];
    const void*  edge_idx  = d_in[1];
    const float* W1        = (const float*)d_in[2];
    const float* att_src1  = (const float*)d_in[3];
    const float* att_dst1  = (const float*)d_in[4];
    const float* b1        = (const float*)d_in[5];
    const float* W2        = (const float*)d_in[6];
    const float* att_src2  = (const float*)d_in[7];
    const float* att_dst2  = (const float*)d_in[8];
    const float* b2        = (const float*)d_in[9];
    float*       out       = (float*)d_out;

    const int N = in_sizes[0] / IN_CH;     // 50000
    const int E = in_sizes[1] / 2;         // 800000
    const int total = E + N;               // 850000

    int warpBlocks = (N * 32 + 255) / 256;

    cudaFuncSetAttribute(k_gemm1,
                         cudaFuncAttributeMaxDynamicSharedMemorySize, G1_SMEM);

    k_zero_detect<<<(N + 255) / 256, 256>>>((const int*)edge_idx, E, N);
    k_hist   <<<(total + 255) / 256, 256>>>(edge_idx, E, total, N);
    k_scan   <<<1, 1024>>>(N);
    k_scatter<<<(total + 255) / 256, 256>>>(edge_idx, E, total, N);

    k_gemm1<<<(N + 63) / 64, 256, G1_SMEM>>>(node_feat, W1, N);
    k_att1 <<<warpBlocks, 256>>>(att_src1, att_dst1, N);
    k_agg1 <<<warpBlocks, 256>>>(b1, N);

    k_gemm2<<<(N + 63) / 64, 320>>>(W2, N);
    k_att2 <<<warpBlocks, 256>>>(att_src2, att_dst2, N);
    k_agg2 <<<warpBlocks, 256>>>(b2, out, N);
}

// round 16
// speedup vs baseline: 1.4938x; 1.2047x over previous
#include <cuda_runtime.h>
#include <cuda_fp16.h>
#include <mma.h>
using namespace nvcuda;

// ---------------- problem constants ----------------
#define N_NODES 50000
#define E_EDGES 800000
#define TE (E_EDGES + N_NODES)   // edges + self-loops
#define IN_CH   128
#define HID2    128              // HEADS*HIDDEN = 2*64
#define OUT_CH  40
#define NEG_SLOPE 0.2f

// gemm1 wmma smem layout
#define WS_LD   136              // halves per W row (16B-pad)
#define XS_LD   136              // halves per x row
#define OUT_LD  132              // floats per out row
#define WS_BYTES (128 * WS_LD * 2)               // 34816
#define XS_BYTES (64 * XS_LD * 2)                // 17408
#define G1_SMEM  (WS_BYTES + XS_BYTES)           // 52224

// gemm2 wmma smem layout
#define XS2_LD   136             // halves per x2 row
#define WS2_LD   48              // halves per W2 row (40 used + 8 zero pad)
#define OUT2_LD  48              // floats per out row
#define XS2_BYTES (128 * XS2_LD * 2)             // 34816
#define WS2_BYTES (128 * WS2_LD * 2)             // 12288
#define G2_SMEM   (XS2_BYTES + WS2_BYTES)        // 47104

// ---------------- scratch (device globals; NEVER touched from host) ----------
__device__ __align__(16) __half g_h1[(size_t)N_NODES * HID2];   // fp16 gather table
__device__ __align__(16) __half g_x2h[(size_t)N_NODES * HID2];  // fp16 layer2 input
__device__ __align__(16) __half g_h2[(size_t)N_NODES * OUT_CH]; // fp16 gather table
__device__ float g_as1[N_NODES * 2];
__device__ float g_ad1[N_NODES * 2];
__device__ float g_as2[N_NODES];
__device__ float g_ad2[N_NODES];
__device__ int   g_deg[N_NODES];
__device__ int   g_off[N_NODES + 1];
__device__ int   g_cur[N_NODES];
__device__ int   g_csr[TE];
__device__ int   g_is64;

// ---------------- helpers ----------------
__device__ __forceinline__ float warp_sum(float v) {
    #pragma unroll
    for (int o = 16; o; o >>= 1) v += __shfl_xor_sync(0xffffffffu, v, o);
    return v;
}
__device__ __forceinline__ float lrelu(float x) {
    return x >= 0.f ? x : NEG_SLOPE * x;
}
__device__ __forceinline__ int edge_val(const void* ei, size_t idx) {
    if (g_is64) return (int)((const long long*)ei)[idx];
    return ((const int*)ei)[idx];
}
__device__ __forceinline__ float4 ld_half4(const __half* p) {
    uint2 rv = *(const uint2*)p;
    float2 f01 = __half22float2(*(__half2*)&rv.x);
    float2 f23 = __half22float2(*(__half2*)&rv.y);
    return make_float4(f01.x, f01.y, f23.x, f23.y);
}
__device__ __forceinline__ uint2 pack_half4(float4 v) {
    __half2 p0 = __float22half2_rn(make_float2(v.x, v.y));
    __half2 p1 = __float22half2_rn(make_float2(v.z, v.w));
    uint2 r;
    r.x = *(unsigned*)&p0;
    r.y = *(unsigned*)&p1;
    return r;
}

// ---------------- zero degrees + detect edge dtype ----------------
__global__ void k_zero_detect(const int* __restrict__ ei32, int E, int N) {
    int i = blockIdx.x * blockDim.x + threadIdx.x;
    if (i < N) g_deg[i] = 0;
    if (i == 0) {
        int nz = 0;
        int stride = E / 64;
        for (int k = 0; k < 64; k++)
            nz |= ei32[2 * (size_t)(k * stride) + 1];
        g_is64 = (nz == 0) ? 1 : 0;
    }
}

// ---------------- CSR build ----------------
__global__ void k_hist(const void* __restrict__ ei, int E, int total, int N) {
    int t = blockIdx.x * blockDim.x + threadIdx.x;
    if (t >= total) return;
    int src, dst;
    if (t < E) { src = edge_val(ei, t); dst = edge_val(ei, (size_t)E + t); }
    else       { src = t - E;           dst = t - E; }
    if ((unsigned)dst >= (unsigned)N || (unsigned)src >= (unsigned)N) return;
    atomicAdd(&g_deg[dst], 1);
}
__global__ void k_scan(int N) {   // single block of 1024
    __shared__ int ssum[1024];
    int t = threadIdx.x;
    int chunk = (N + 1023) / 1024;
    int s = t * chunk;
    int e = min(N, s + chunk);
    int sum = 0;
    for (int i = s; i < e; i++) sum += g_deg[i];
    ssum[t] = sum;
    __syncthreads();
    for (int o = 1; o < 1024; o <<= 1) {
        int v = (t >= o) ? ssum[t - o] : 0;
        __syncthreads();
        ssum[t] += v;
        __syncthreads();
    }
    int run = (t > 0) ? ssum[t - 1] : 0;
    for (int i = s; i < e; i++) {
        g_off[i] = run; g_cur[i] = run;
        run += g_deg[i];
    }
    if (s < N && e == N) g_off[N] = run;
}
__global__ void k_scatter(const void* __restrict__ ei, int E, int total, int N) {
    int t = blockIdx.x * blockDim.x + threadIdx.x;
    if (t >= total) return;
    int src, dst;
    if (t < E) { src = edge_val(ei, t); dst = edge_val(ei, (size_t)E + t); }
    else       { src = t - E;           dst = t - E; }
    if ((unsigned)dst >= (unsigned)N || (unsigned)src >= (unsigned)N) return;
    int pos = atomicAdd(&g_cur[dst], 1);
    g_csr[pos] = src;
}

// ---------------- GEMM1 (wmma) + fused att1 -----------------------------------
// 64 rows x 128 cols per block, 256 threads = 8 warps (4x2).
__global__ void k_gemm1(const float* __restrict__ x, const float* __restrict__ W,
                        const float* __restrict__ att_src,
                        const float* __restrict__ att_dst, int N) {
    extern __shared__ char smraw[];
    __half* Ws   = (__half*)smraw;                 // [128][WS_LD]
    __half* xs   = (__half*)(smraw + WS_BYTES);    // [64][XS_LD]
    float*  outf = (float*)smraw;                  // [64][OUT_LD] epilogue alias

    int tid = threadIdx.x;
    int nb = blockIdx.x * 64;

    const float4* Wf4 = (const float4*)W;
    for (int i = tid; i < 128 * 32; i += 256) {
        int r = i >> 5, c = (i & 31) * 4;
        float4 v = Wf4[i];
        __half2* p = (__half2*)(Ws + r * WS_LD + c);
        p[0] = __float22half2_rn(make_float2(v.x, v.y));
        p[1] = __float22half2_rn(make_float2(v.z, v.w));
    }
    for (int i = tid; i < 64 * 32; i += 256) {
        int r = i >> 5, c = (i & 31) * 4;
        float4 v = (nb + r < N) ? *(const float4*)(x + (size_t)(nb + r) * 128 + c)
                                : make_float4(0.f, 0.f, 0.f, 0.f);
        __half2* p = (__half2*)(xs + r * XS_LD + c);
        p[0] = __float22half2_rn(make_float2(v.x, v.y));
        p[1] = __float22half2_rn(make_float2(v.z, v.w));
    }
    __syncthreads();

    int wid = tid >> 5;
    int wr = wid >> 1;
    int wc = wid & 1;

    wmma::fragment<wmma::accumulator, 16, 16, 16, float> acc[4];
    #pragma unroll
    for (int f = 0; f < 4; f++) wmma::fill_fragment(acc[f], 0.f);

    #pragma unroll
    for (int k = 0; k < 8; k++) {
        wmma::fragment<wmma::matrix_a, 16, 16, 16, __half, wmma::row_major> a;
        wmma::load_matrix_sync(a, xs + (wr * 16) * XS_LD + k * 16, XS_LD);
        #pragma unroll
        for (int f = 0; f < 4; f++) {
            wmma::fragment<wmma::matrix_b, 16, 16, 16, __half, wmma::row_major> b;
            wmma::load_matrix_sync(b, Ws + (k * 16) * WS_LD + wc * 64 + f * 16, WS_LD);
            wmma::mma_sync(acc[f], a, b, acc[f]);
        }
    }
    __syncthreads();   // done reading Ws/xs; alias as outf

    #pragma unroll
    for (int f = 0; f < 4; f++)
        wmma::store_matrix_sync(outf + (wr * 16) * OUT_LD + wc * 64 + f * 16,
                                acc[f], OUT_LD, wmma::mem_row_major);
    __syncthreads();

    // fp32 smem -> fp16 global (coalesced 8B stores)
    for (int i = tid; i < 64 * 32; i += 256) {
        int r = i >> 5, c = (i & 31) * 4;
        if (nb + r < N) {
            float4 v = *(const float4*)(outf + r * OUT_LD + c);
            *(uint2*)(g_h1 + (size_t)(nb + r) * 128 + c) = pack_half4(v);
        }
    }

    // fused att1: warp w handles rows w*8..w*8+7
    int lane = tid & 31;
    float4 a = *(const float4*)(att_src + 4 * lane);
    float4 d = *(const float4*)(att_dst + 4 * lane);
    #pragma unroll
    for (int t = 0; t < 8; t++) {
        int r = wid * 8 + t;
        float4 h = *(const float4*)(outf + r * OUT_LD + 4 * lane);
        float as = h.x * a.x + h.y * a.y + h.z * a.z + h.w * a.w;
        float ad = h.x * d.x + h.y * d.y + h.z * d.z + h.w * d.w;
        #pragma unroll
        for (int o = 8; o; o >>= 1) {
            as += __shfl_xor_sync(0xffffffffu, as, o);
            ad += __shfl_xor_sync(0xffffffffu, ad, o);
        }
        float as1v = __shfl_sync(0xffffffffu, as, 16);
        float ad1v = __shfl_sync(0xffffffffu, ad, 16);
        if (lane == 0 && nb + r < N) {
            g_as1[2 * (nb + r)]     = as;  g_as1[2 * (nb + r) + 1] = as1v;
            g_ad1[2 * (nb + r)]     = ad;  g_ad1[2 * (nb + r) + 1] = ad1v;
        }
    }
}

// ---------------- aggregation layer 1 (warp per node, fp16 gather/store) ------
__global__ void k_agg1(const float* __restrict__ b1, int N) {
    int warp = (blockIdx.x * blockDim.x + threadIdx.x) >> 5;
    int lane = threadIdx.x & 31;
    if (warp >= N) return;
    int n = warp;
    int s = g_off[n], epn = g_off[n + 1];
    float ad0 = g_ad1[2 * n], ad1 = g_ad1[2 * n + 1];
    bool head0 = (lane < 16);

    float4 acc = make_float4(0.f, 0.f, 0.f, 0.f);
    float den0 = 0.f, den1 = 0.f;

    for (int j0 = s; j0 < epn; j0 += 32) {
        int j = j0 + lane;
        int sc = 0; float w0 = 0.f, w1 = 0.f;
        if (j < epn) {
            sc = g_csr[j];
            float2 as = *(const float2*)(g_as1 + 2 * sc);
            w0 = __expf(lrelu(as.x + ad0));
            w1 = __expf(lrelu(as.y + ad1));
        }
        den0 += w0; den1 += w1;
        int cnt = min(32, epn - j0);
        int i = 0;
        #define STEP(u) {                                                   \
            int   ss = __shfl_sync(0xffffffffu, sc, i + (u));               \
            float wa = __shfl_sync(0xffffffffu, w0, i + (u));               \
            float wb = __shfl_sync(0xffffffffu, w1, i + (u));               \
            float ww = head0 ? wa : wb;                                     \
            float4 v = ld_half4(g_h1 + (size_t)ss * 128 + 4 * lane);        \
            acc.x += ww * v.x; acc.y += ww * v.y;                           \
            acc.z += ww * v.z; acc.w += ww * v.w; }
        for (; i + 8 <= cnt; i += 8) {
            STEP(0) STEP(1) STEP(2) STEP(3) STEP(4) STEP(5) STEP(6) STEP(7)
        }
        for (; i < cnt; i++) { STEP(0) }
        #undef STEP
    }
    den0 = warp_sum(den0) + 1e-16f;
    den1 = warp_sum(den1) + 1e-16f;
    float den = head0 ? den0 : den1;

    float4 bb = *(const float4*)(b1 + 4 * lane);
    float o0 = acc.x / den + bb.x;
    float o1 = acc.y / den + bb.y;
    float o2 = acc.z / den + bb.z;
    float o3 = acc.w / den + bb.w;
    o0 = o0 > 0.f ? o0 : (__expf(o0) - 1.f);
    o1 = o1 > 0.f ? o1 : (__expf(o1) - 1.f);
    o2 = o2 > 0.f ? o2 : (__expf(o2) - 1.f);
    o3 = o3 > 0.f ? o3 : (__expf(o3) - 1.f);
    *(uint2*)(g_x2h + (size_t)n * 128 + 4 * lane) =
        pack_half4(make_float4(o0, o1, o2, o3));
}

// ---------------- GEMM2 (wmma) + fused att2 -----------------------------------
// 128 rows x 48 cols (40 used) per block, 256 threads = 8 warps, warp = 16 rows.
__global__ void k_gemm2(const float* __restrict__ W,
                        const float* __restrict__ att_src,
                        const float* __restrict__ att_dst, int N) {
    extern __shared__ char smraw[];
    __half* xs   = (__half*)smraw;                  // [128][XS2_LD]
    __half* Ws   = (__half*)(smraw + XS2_BYTES);    // [128][WS2_LD]
    float*  outf = (float*)smraw;                   // [128][OUT2_LD] alias (24576B)

    int tid = threadIdx.x;
    int nb = blockIdx.x * 128;

    // x2 fp16 tile: 128 rows x 16 uint4 chunks (8 halves each = 128 halves/row)
    for (int i = tid; i < 128 * 16; i += 256) {
        int r = i >> 4, c = (i & 15) * 8;
        uint4 v = (nb + r < N) ? *(const uint4*)(g_x2h + (size_t)(nb + r) * 128 + c)
                               : make_uint4(0u, 0u, 0u, 0u);
        *(uint4*)(xs + r * XS2_LD + c) = v;
    }
    // W2 fp32 -> fp16 smem, pad cols 40..47 with zeros
    for (int i = tid; i < 128 * 40; i += 256) {
        int r = i / 40, c = i % 40;
        Ws[r * WS2_LD + c] = __float2half_rn(W[i]);
    }
    for (int i = tid; i < 128 * 8; i += 256) {
        int r = i >> 3, c = 40 + (i & 7);
        Ws[r * WS2_LD + c] = __float2half_rn(0.f);
    }
    __syncthreads();

    int wid = tid >> 5;
    int lane = tid & 31;

    wmma::fragment<wmma::accumulator, 16, 16, 16, float> acc[3];
    #pragma unroll
    for (int f = 0; f < 3; f++) wmma::fill_fragment(acc[f], 0.f);

    #pragma unroll
    for (int k = 0; k < 8; k++) {
        wmma::fragment<wmma::matrix_a, 16, 16, 16, __half, wmma::row_major> a;
        wmma::load_matrix_sync(a, xs + (wid * 16) * XS2_LD + k * 16, XS2_LD);
        #pragma unroll
        for (int f = 0; f < 3; f++) {
            wmma::fragment<wmma::matrix_b, 16, 16, 16, __half, wmma::row_major> b;
            wmma::load_matrix_sync(b, Ws + (k * 16) * WS2_LD + f * 16, WS2_LD);
            wmma::mma_sync(acc[f], a, b, acc[f]);
        }
    }
    __syncthreads();   // done reading xs; alias as outf

    #pragma unroll
    for (int f = 0; f < 3; f++)
        wmma::store_matrix_sync(outf + (wid * 16) * OUT2_LD + f * 16,
                                acc[f], OUT2_LD, wmma::mem_row_major);
    __syncthreads();

    // fp32 smem -> fp16 global: 128 rows x 10 uint2 chunks (40 halves/row)
    for (int i = tid; i < 128 * 10; i += 256) {
        int r = i / 10, c = (i % 10) * 4;
        if (nb + r < N) {
            float4 v = *(const float4*)(outf + r * OUT2_LD + c);
            *(uint2*)(g_h2 + (size_t)(nb + r) * 40 + c) = pack_half4(v);
        }
    }

    // fused att2: warp w handles rows w*16..w*16+15; lanes 0..9 hold 4 cols each
    float4 av = make_float4(0.f, 0.f, 0.f, 0.f), dv = av;
    if (lane < 10) {
        av = *(const float4*)(att_src + 4 * lane);
        dv = *(const float4*)(att_dst + 4 * lane);
    }
    #pragma unroll
    for (int t = 0; t < 16; t++) {
        int r = wid * 16 + t;
        float as = 0.f, ad = 0.f;
        if (lane < 10) {
            float4 h = *(const float4*)(outf + r * OUT2_LD + 4 * lane);
            as = h.x * av.x + h.y * av.y + h.z * av.z + h.w * av.w;
            ad = h.x * dv.x + h.y * dv.y + h.z * dv.z + h.w * dv.w;
        }
        as = warp_sum(as); ad = warp_sum(ad);
        if (lane == 0 && nb + r < N) {
            g_as2[nb + r] = as;
            g_ad2[nb + r] = ad;
        }
    }
}

// ---------------- aggregation layer 2 (warp per node, fp16 gather) ------------
__global__ void k_agg2(const float* __restrict__ b2, float* __restrict__ out, int N) {
    int warp = (blockIdx.x * blockDim.x + threadIdx.x) >> 5;
    int lane = threadIdx.x & 31;
    if (warp >= N) return;
    int n = warp;
    int s = g_off[n], epn = g_off[n + 1];
    float adn = g_ad2[n];
    int u = lane / 10;        // src slot 0..2 (u==3: lanes 30,31 inactive)
    int v = lane - u * 10;    // half4 chunk 0..9

    float4 acc = make_float4(0.f, 0.f, 0.f, 0.f);
    float den = 0.f;
    for (int j0 = s; j0 < epn; j0 += 32) {
        int j = j0 + lane;
        int sc = 0; float w = 0.f;
        if (j < epn) {
            sc = g_csr[j];
            w = __expf(lrelu(g_as2[sc] + adn));
        }
        den += w;
        int cnt = min(32, epn - j0);
        for (int i = 0; i < cnt; i += 3) {
            int e = i + u;
            int es = min(e, cnt - 1);
            int   ss = __shfl_sync(0xffffffffu, sc, es);
            float ww = __shfl_sync(0xffffffffu, w,  es);
            if (e < cnt && u < 3) {
                float4 hv = ld_half4(g_h2 + (size_t)ss * 40 + 4 * v);
                acc.x += ww * hv.x; acc.y += ww * hv.y;
                acc.z += ww * hv.z; acc.w += ww * hv.w;
            }
        }
    }
    den = warp_sum(den) + 1e-16f;
    float4 t1, t2;
    t1.x = __shfl_down_sync(0xffffffffu, acc.x, 10);
    t1.y = __shfl_down_sync(0xffffffffu, acc.y, 10);
    t1.z = __shfl_down_sync(0xffffffffu, acc.z, 10);
    t1.w = __shfl_down_sync(0xffffffffu, acc.w, 10);
    t2.x = __shfl_down_sync(0xffffffffu, acc.x, 20);
    t2.y = __shfl_down_sync(0xffffffffu, acc.y, 20);
    t2.z = __shfl_down_sync(0xffffffffu, acc.z, 20);
    t2.w = __shfl_down_sync(0xffffffffu, acc.w, 20);
    if (lane < 10) {
        float4 bb = *(const float4*)(b2 + 4 * lane);
        float4 o;
        o.x = (acc.x + t1.x + t2.x) / den + bb.x;
        o.y = (acc.y + t1.y + t2.y) / den + bb.y;
        o.z = (acc.z + t1.z + t2.z) / den + bb.z;
        o.w = (acc.w + t1.w + t2.w) / den + bb.w;
        *(float4*)(out + (size_t)n * 40 + 4 * lane) = o;
    }
}

// ---------------- launch ----------------
extern "C" void kernel_launch(void* const* d_in, const int* in_sizes, int n_in,
                              void* d_out, int out_size) {
    const float* node_feat = (const float*)d_in[0];
    const void*  edge_idx  = d_in[1];
    const float* W1        = (const float*)d_in[2];
    const float* att_src1  = (const float*)d_in[3];
    const float* att_dst1  = (const float*)d_in[4];
    const float* b1        = (const float*)d_in[5];
    const float* W2        = (const float*)d_in[6];
    const float* att_src2  = (const float*)d_in[7];
    const float* att_dst2  = (const float*)d_in[8];
    const float* b2        = (const float*)d_in[9];
    float*       out       = (float*)d_out;

    const int N = in_sizes[0] / IN_CH;     // 50000
    const int E = in_sizes[1] / 2;         // 800000
    const int total = E + N;               // 850000

    int warpBlocks = (N * 32 + 255) / 256;

    cudaFuncSetAttribute(k_gemm1,
                         cudaFuncAttributeMaxDynamicSharedMemorySize, G1_SMEM);
    cudaFuncSetAttribute(k_gemm2,
                         cudaFuncAttributeMaxDynamicSharedMemorySize, G2_SMEM);

    k_zero_detect<<<(N + 255) / 256, 256>>>((const int*)edge_idx, E, N);
    k_hist   <<<(total + 255) / 256, 256>>>(edge_idx, E, total, N);
    k_scan   <<<1, 1024>>>(N);
    k_scatter<<<(total + 255) / 256, 256>>>(edge_idx, E, total, N);

    k_gemm1<<<(N + 63) / 64, 256, G1_SMEM>>>(node_feat, W1, att_src1, att_dst1, N);
    k_agg1 <<<warpBlocks, 256>>>(b1, N);

    k_gemm2<<<(N + 127) / 128, 256, G2_SMEM>>>(W2, att_src2, att_dst2, N);
    k_agg2 <<<warpBlocks, 256>>>(b2, out, N);
}

// round 17
// speedup vs baseline: 1.9115x; 1.2797x over previous
#include <cuda_runtime.h>
#include <cuda_fp16.h>
#include <mma.h>
using namespace nvcuda;

// ---------------- problem constants ----------------
#define N_NODES 50000
#define E_EDGES 800000
#define TE (E_EDGES + N_NODES)   // edges + self-loops
#define IN_CH   128
#define HID2    128              // HEADS*HIDDEN = 2*64
#define OUT_CH  40
#define NEG_SLOPE 0.2f

// gemm1 wmma smem layout
#define WS_LD   136              // halves per W row (16B-pad)
#define XS_LD   136              // halves per x row
#define OUT_LD  132              // floats per out row
#define WS_BYTES (128 * WS_LD * 2)               // 34816
#define XS_BYTES (64 * XS_LD * 2)                // 17408
#define G1_SMEM  (WS_BYTES + XS_BYTES)           // 52224

// gemm2 wmma smem layout
#define XS2_LD   136             // halves per x2 row
#define WS2_LD   48              // halves per W2 row (40 used + 8 zero pad)
#define OUT2_LD  48              // floats per out row
#define XS2_BYTES (128 * XS2_LD * 2)             // 34816
#define WS2_BYTES (128 * WS2_LD * 2)             // 12288
#define G2_SMEM   (XS2_BYTES + WS2_BYTES)        // 47104

// ---------------- scratch (device globals; NEVER touched from host) ----------
__device__ __align__(16) __half g_h1[(size_t)N_NODES * HID2];   // fp16 gather table
__device__ __align__(16) __half g_x2h[(size_t)N_NODES * HID2];  // fp16 layer2 input
__device__ __align__(16) __half g_h2[(size_t)N_NODES * OUT_CH]; // fp16 gather table
__device__ float g_as1[N_NODES * 2];
__device__ float g_ad1[N_NODES * 2];
__device__ float g_as2[N_NODES];
__device__ float g_ad2[N_NODES];
__device__ __align__(16) int g_deg[N_NODES];
__device__ __align__(16) int g_off[N_NODES + 4];
__device__ __align__(16) int g_cur[N_NODES + 4];
__device__ int   g_csr[TE];
__device__ int   g_is64;

// ---------------- helpers ----------------
__device__ __forceinline__ float warp_sum(float v) {
    #pragma unroll
    for (int o = 16; o; o >>= 1) v += __shfl_xor_sync(0xffffffffu, v, o);
    return v;
}
__device__ __forceinline__ float lrelu(float x) {
    return x >= 0.f ? x : NEG_SLOPE * x;
}
__device__ __forceinline__ int edge_val(const void* ei, size_t idx) {
    if (g_is64) return (int)((const long long*)ei)[idx];
    return ((const int*)ei)[idx];
}
__device__ __forceinline__ float4 ld_half4(const __half* p) {
    uint2 rv = *(const uint2*)p;
    float2 f01 = __half22float2(*(__half2*)&rv.x);
    float2 f23 = __half22float2(*(__half2*)&rv.y);
    return make_float4(f01.x, f01.y, f23.x, f23.y);
}
__device__ __forceinline__ uint2 pack_half4(float4 v) {
    __half2 p0 = __float22half2_rn(make_float2(v.x, v.y));
    __half2 p1 = __float22half2_rn(make_float2(v.z, v.w));
    uint2 r;
    r.x = *(unsigned*)&p0;
    r.y = *(unsigned*)&p1;
    return r;
}

// ---------------- zero degrees + detect edge dtype ----------------
__global__ void k_zero_detect(const int* __restrict__ ei32, int E, int N) {
    int i = blockIdx.x * blockDim.x + threadIdx.x;
    if (i < N) g_deg[i] = 0;
    if (i == 0) {
        int nz = 0;
        int stride = E / 64;
        for (int k = 0; k < 64; k++)
            nz |= ei32[2 * (size_t)(k * stride) + 1];
        g_is64 = (nz == 0) ? 1 : 0;
    }
}

// ---------------- CSR build ----------------
__global__ void k_hist(const void* __restrict__ ei, int E, int total, int N) {
    int t = blockIdx.x * blockDim.x + threadIdx.x;
    if (t >= total) return;
    int src, dst;
    if (t < E) { src = edge_val(ei, t); dst = edge_val(ei, (size_t)E + t); }
    else       { src = t - E;           dst = t - E; }
    if ((unsigned)dst >= (unsigned)N || (unsigned)src >= (unsigned)N) return;
    atomicAdd(&g_deg[dst], 1);
}
// single block of 1024; vectorized int4 passes (chunk multiple of 4)
__global__ void k_scan(int N) {
    __shared__ int ssum[1024];
    int t = threadIdx.x;
    int chunk = (((N + 1023) / 1024) + 3) & ~3;   // multiple of 4
    int s = t * chunk;
    int e = min(N, s + chunk);
    int sum = 0;
    if (s < N) {
        int m = e - s;
        int full = m >> 2;
        const int4* p = (const int4*)(g_deg + s);
        for (int i = 0; i < full; i++) {
            int4 v = p[i];
            sum += v.x + v.y + v.z + v.w;
        }
        for (int i = full * 4; i < m; i++) sum += g_deg[s + i];
    }
    ssum[t] = sum;
    __syncthreads();
    for (int o = 1; o < 1024; o <<= 1) {
        int v = (t >= o) ? ssum[t - o] : 0;
        __syncthreads();
        ssum[t] += v;
        __syncthreads();
    }
    int run = (t > 0) ? ssum[t - 1] : 0;
    if (s < N) {
        int m = e - s;
        int full = m >> 2;
        const int4* p = (const int4*)(g_deg + s);
        int4* po = (int4*)(g_off + s);
        int4* pc = (int4*)(g_cur + s);
        for (int i = 0; i < full; i++) {
            int4 d = p[i];
            int4 o4;
            o4.x = run; run += d.x;
            o4.y = run; run += d.y;
            o4.z = run; run += d.z;
            o4.w = run; run += d.w;
            po[i] = o4; pc[i] = o4;
        }
        for (int i = full * 4; i < m; i++) {
            g_off[s + i] = run; g_cur[s + i] = run;
            run += g_deg[s + i];
        }
        if (e == N) g_off[N] = run;
    }
}
__global__ void k_scatter(const void* __restrict__ ei, int E, int total, int N) {
    int t = blockIdx.x * blockDim.x + threadIdx.x;
    if (t >= total) return;
    int src, dst;
    if (t < E) { src = edge_val(ei, t); dst = edge_val(ei, (size_t)E + t); }
    else       { src = t - E;           dst = t - E; }
    if ((unsigned)dst >= (unsigned)N || (unsigned)src >= (unsigned)N) return;
    int pos = atomicAdd(&g_cur[dst], 1);
    g_csr[pos] = src;
}

// ---------------- GEMM1 (wmma) + fused att1 -----------------------------------
// 64 rows x 128 cols per block, 256 threads = 8 warps (4x2).
__global__ void k_gemm1(const float* __restrict__ x, const float* __restrict__ W,
                        const float* __restrict__ att_src,
                        const float* __restrict__ att_dst, int N) {
    extern __shared__ char smraw[];
    __half* Ws   = (__half*)smraw;                 // [128][WS_LD]
    __half* xs   = (__half*)(smraw + WS_BYTES);    // [64][XS_LD]
    float*  outf = (float*)smraw;                  // [64][OUT_LD] epilogue alias

    int tid = threadIdx.x;
    int nb = blockIdx.x * 64;

    const float4* Wf4 = (const float4*)W;
    for (int i = tid; i < 128 * 32; i += 256) {
        int r = i >> 5, c = (i & 31) * 4;
        float4 v = Wf4[i];
        __half2* p = (__half2*)(Ws + r * WS_LD + c);
        p[0] = __float22half2_rn(make_float2(v.x, v.y));
        p[1] = __float22half2_rn(make_float2(v.z, v.w));
    }
    for (int i = tid; i < 64 * 32; i += 256) {
        int r = i >> 5, c = (i & 31) * 4;
        float4 v = (nb + r < N) ? *(const float4*)(x + (size_t)(nb + r) * 128 + c)
                                : make_float4(0.f, 0.f, 0.f, 0.f);
        __half2* p = (__half2*)(xs + r * XS_LD + c);
        p[0] = __float22half2_rn(make_float2(v.x, v.y));
        p[1] = __float22half2_rn(make_float2(v.z, v.w));
    }
    __syncthreads();

    int wid = tid >> 5;
    int wr = wid >> 1;
    int wc = wid & 1;

    wmma::fragment<wmma::accumulator, 16, 16, 16, float> acc[4];
    #pragma unroll
    for (int f = 0; f < 4; f++) wmma::fill_fragment(acc[f], 0.f);

    #pragma unroll
    for (int k = 0; k < 8; k++) {
        wmma::fragment<wmma::matrix_a, 16, 16, 16, __half, wmma::row_major> a;
        wmma::load_matrix_sync(a, xs + (wr * 16) * XS_LD + k * 16, XS_LD);
        #pragma unroll
        for (int f = 0; f < 4; f++) {
            wmma::fragment<wmma::matrix_b, 16, 16, 16, __half, wmma::row_major> b;
            wmma::load_matrix_sync(b, Ws + (k * 16) * WS_LD + wc * 64 + f * 16, WS_LD);
            wmma::mma_sync(acc[f], a, b, acc[f]);
        }
    }
    __syncthreads();   // done reading Ws/xs; alias as outf

    #pragma unroll
    for (int f = 0; f < 4; f++)
        wmma::store_matrix_sync(outf + (wr * 16) * OUT_LD + wc * 64 + f * 16,
                                acc[f], OUT_LD, wmma::mem_row_major);
    __syncthreads();

    // fp32 smem -> fp16 global (coalesced 8B stores)
    for (int i = tid; i < 64 * 32; i += 256) {
        int r = i >> 5, c = (i & 31) * 4;
        if (nb + r < N) {
            float4 v = *(const float4*)(outf + r * OUT_LD + c);
            *(uint2*)(g_h1 + (size_t)(nb + r) * 128 + c) = pack_half4(v);
        }
    }

    // fused att1: warp w handles rows w*8..w*8+7
    int lane = tid & 31;
    float4 a = *(const float4*)(att_src + 4 * lane);
    float4 d = *(const float4*)(att_dst + 4 * lane);
    #pragma unroll
    for (int t = 0; t < 8; t++) {
        int r = wid * 8 + t;
        float4 h = *(const float4*)(outf + r * OUT_LD + 4 * lane);
        float as = h.x * a.x + h.y * a.y + h.z * a.z + h.w * a.w;
        float ad = h.x * d.x + h.y * d.y + h.z * d.z + h.w * d.w;
        #pragma unroll
        for (int o = 8; o; o >>= 1) {
            as += __shfl_xor_sync(0xffffffffu, as, o);
            ad += __shfl_xor_sync(0xffffffffu, ad, o);
        }
        float as1v = __shfl_sync(0xffffffffu, as, 16);
        float ad1v = __shfl_sync(0xffffffffu, ad, 16);
        if (lane == 0 && nb + r < N) {
            g_as1[2 * (nb + r)]     = as;  g_as1[2 * (nb + r) + 1] = as1v;
            g_ad1[2 * (nb + r)]     = ad;  g_ad1[2 * (nb + r) + 1] = ad1v;
        }
    }
}

// ---------------- aggregation layer 1 (warp per node, fp16 gather/store) ------
__global__ void k_agg1(const float* __restrict__ b1, int N) {
    int warp = (blockIdx.x * blockDim.x + threadIdx.x) >> 5;
    int lane = threadIdx.x & 31;
    if (warp >= N) return;
    int n = warp;
    int s = g_off[n], epn = g_off[n + 1];
    float ad0 = g_ad1[2 * n], ad1 = g_ad1[2 * n + 1];
    bool head0 = (lane < 16);

    float4 acc = make_float4(0.f, 0.f, 0.f, 0.f);
    float den0 = 0.f, den1 = 0.f;

    for (int j0 = s; j0 < epn; j0 += 32) {
        int j = j0 + lane;
        int sc = 0; float w0 = 0.f, w1 = 0.f;
        if (j < epn) {
            sc = g_csr[j];
            float2 as = *(const float2*)(g_as1 + 2 * sc);
            w0 = __expf(lrelu(as.x + ad0));
            w1 = __expf(lrelu(as.y + ad1));
        }
        den0 += w0; den1 += w1;
        int cnt = min(32, epn - j0);
        int i = 0;
        #define STEP(u) {                                                   \
            int   ss = __shfl_sync(0xffffffffu, sc, i + (u));               \
            float wa = __shfl_sync(0xffffffffu, w0, i + (u));               \
            float wb = __shfl_sync(0xffffffffu, w1, i + (u));               \
            float ww = head0 ? wa : wb;                                     \
            float4 v = ld_half4(g_h1 + (size_t)ss * 128 + 4 * lane);        \
            acc.x += ww * v.x; acc.y += ww * v.y;                           \
            acc.z += ww * v.z; acc.w += ww * v.w; }
        for (; i + 8 <= cnt; i += 8) {
            STEP(0) STEP(1) STEP(2) STEP(3) STEP(4) STEP(5) STEP(6) STEP(7)
        }
        for (; i < cnt; i++) { STEP(0) }
        #undef STEP
    }
    den0 = warp_sum(den0) + 1e-16f;
    den1 = warp_sum(den1) + 1e-16f;
    float den = head0 ? den0 : den1;

    float4 bb = *(const float4*)(b1 + 4 * lane);
    float o0 = acc.x / den + bb.x;
    float o1 = acc.y / den + bb.y;
    float o2 = acc.z / den + bb.z;
    float o3 = acc.w / den + bb.w;
    o0 = o0 > 0.f ? o0 : (__expf(o0) - 1.f);
    o1 = o1 > 0.f ? o1 : (__expf(o1) - 1.f);
    o2 = o2 > 0.f ? o2 : (__expf(o2) - 1.f);
    o3 = o3 > 0.f ? o3 : (__expf(o3) - 1.f);
    *(uint2*)(g_x2h + (size_t)n * 128 + 4 * lane) =
        pack_half4(make_float4(o0, o1, o2, o3));
}

// ---------------- GEMM2 (wmma) + fused att2 -----------------------------------
// 128 rows x 48 cols (40 used) per block, 256 threads = 8 warps, warp = 16 rows.
__global__ void k_gemm2(const float* __restrict__ W,
                        const float* __restrict__ att_src,
                        const float* __restrict__ att_dst, int N) {
    extern __shared__ char smraw[];
    __half* xs   = (__half*)smraw;                  // [128][XS2_LD]
    __half* Ws   = (__half*)(smraw + XS2_BYTES);    // [128][WS2_LD]
    float*  outf = (float*)smraw;                   // [128][OUT2_LD] alias (24576B)

    int tid = threadIdx.x;
    int nb = blockIdx.x * 128;

    // x2 fp16 tile: 128 rows x 16 uint4 chunks (8 halves each = 128 halves/row)
    for (int i = tid; i < 128 * 16; i += 256) {
        int r = i >> 4, c = (i & 15) * 8;
        uint4 v = (nb + r < N) ? *(const uint4*)(g_x2h + (size_t)(nb + r) * 128 + c)
                               : make_uint4(0u, 0u, 0u, 0u);
        *(uint4*)(xs + r * XS2_LD + c) = v;
    }
    // W2 fp32 -> fp16 smem, pad cols 40..47 with zeros
    for (int i = tid; i < 128 * 40; i += 256) {
        int r = i / 40, c = i % 40;
        Ws[r * WS2_LD + c] = __float2half_rn(W[i]);
    }
    for (int i = tid; i < 128 * 8; i += 256) {
        int r = i >> 3, c = 40 + (i & 7);
        Ws[r * WS2_LD + c] = __float2half_rn(0.f);
    }
    __syncthreads();

    int wid = tid >> 5;
    int lane = tid & 31;

    wmma::fragment<wmma::accumulator, 16, 16, 16, float> acc[3];
    #pragma unroll
    for (int f = 0; f < 3; f++) wmma::fill_fragment(acc[f], 0.f);

    #pragma unroll
    for (int k = 0; k < 8; k++) {
        wmma::fragment<wmma::matrix_a, 16, 16, 16, __half, wmma::row_major> a;
        wmma::load_matrix_sync(a, xs + (wid * 16) * XS2_LD + k * 16, XS2_LD);
        #pragma unroll
        for (int f = 0; f < 3; f++) {
            wmma::fragment<wmma::matrix_b, 16, 16, 16, __half, wmma::row_major> b;
            wmma::load_matrix_sync(b, Ws + (k * 16) * WS2_LD + f * 16, WS2_LD);
            wmma::mma_sync(acc[f], a, b, acc[f]);
        }
    }
    __syncthreads();   // done reading xs; alias as outf

    #pragma unroll
    for (int f = 0; f < 3; f++)
        wmma::store_matrix_sync(outf + (wid * 16) * OUT2_LD + f * 16,
                                acc[f], OUT2_LD, wmma::mem_row_major);
    __syncthreads();

    // fp32 smem -> fp16 global: 128 rows x 10 uint2 chunks (40 halves/row)
    for (int i = tid; i < 128 * 10; i += 256) {
        int r = i / 10, c = (i % 10) * 4;
        if (nb + r < N) {
            float4 v = *(const float4*)(outf + r * OUT2_LD + c);
            *(uint2*)(g_h2 + (size_t)(nb + r) * 40 + c) = pack_half4(v);
        }
    }

    // fused att2: warp w handles rows w*16..w*16+15; lanes 0..9 hold 4 cols each
    float4 av = make_float4(0.f, 0.f, 0.f, 0.f), dv = av;
    if (lane < 10) {
        av = *(const float4*)(att_src + 4 * lane);
        dv = *(const float4*)(att_dst + 4 * lane);
    }
    #pragma unroll
    for (int t = 0; t < 16; t++) {
        int r = wid * 16 + t;
        float as = 0.f, ad = 0.f;
        if (lane < 10) {
            float4 h = *(const float4*)(outf + r * OUT2_LD + 4 * lane);
            as = h.x * av.x + h.y * av.y + h.z * av.z + h.w * av.w;
            ad = h.x * dv.x + h.y * dv.y + h.z * dv.z + h.w * dv.w;
        }
        as = warp_sum(as); ad = warp_sum(ad);
        if (lane == 0 && nb + r < N) {
            g_as2[nb + r] = as;
            g_ad2[nb + r] = ad;
        }
    }
}

// ---------------- aggregation layer 2 (warp per node, fp16 gather) ------------
__global__ void k_agg2(const float* __restrict__ b2, float* __restrict__ out, int N) {
    int warp = (blockIdx.x * blockDim.x + threadIdx.x) >> 5;
    int lane = threadIdx.x & 31;
    if (warp >= N) return;
    int n = warp;
    int s = g_off[n], epn = g_off[n + 1];
    float adn = g_ad2[n];
    int u = lane / 10;        // src slot 0..2 (u==3: lanes 30,31 inactive)
    int v = lane - u * 10;    // half4 chunk 0..9

    float4 acc = make_float4(0.f, 0.f, 0.f, 0.f);
    float den = 0.f;
    for (int j0 = s; j0 < epn; j0 += 32) {
        int j = j0 + lane;
        int sc = 0; float w = 0.f;
        if (j < epn) {
            sc = g_csr[j];
            w = __expf(lrelu(g_as2[sc] + adn));
        }
        den += w;
        int cnt = min(32, epn - j0);
        for (int i = 0; i < cnt; i += 3) {
            int e = i + u;
            int es = min(e, cnt - 1);
            int   ss = __shfl_sync(0xffffffffu, sc, es);
            float ww = __shfl_sync(0xffffffffu, w,  es);
            if (e < cnt && u < 3) {
                float4 hv = ld_half4(g_h2 + (size_t)ss * 40 + 4 * v);
                acc.x += ww * hv.x; acc.y += ww * hv.y;
                acc.z += ww * hv.z; acc.w += ww * hv.w;
            }
        }
    }
    den = warp_sum(den) + 1e-16f;
    float4 t1, t2;
    t1.x = __shfl_down_sync(0xffffffffu, acc.x, 10);
    t1.y = __shfl_down_sync(0xffffffffu, acc.y, 10);
    t1.z = __shfl_down_sync(0xffffffffu, acc.z, 10);
    t1.w = __shfl_down_sync(0xffffffffu, acc.w, 10);
    t2.x = __shfl_down_sync(0xffffffffu, acc.x, 20);
    t2.y = __shfl_down_sync(0xffffffffu, acc.y, 20);
    t2.z = __shfl_down_sync(0xffffffffu, acc.z, 20);
    t2.w = __shfl_down_sync(0xffffffffu, acc.w, 20);
    if (lane < 10) {
        float4 bb = *(const float4*)(b2 + 4 * lane);
        float4 o;
        o.x = (acc.x + t1.x + t2.x) / den + bb.x;
        o.y = (acc.y + t1.y + t2.y) / den + bb.y;
        o.z = (acc.z + t1.z + t2.z) / den + bb.z;
        o.w = (acc.w + t1.w + t2.w) / den + bb.w;
        *(float4*)(out + (size_t)n * 40 + 4 * lane) = o;
    }
}

// ---------------- launch: fork CSR chain || gemm1, join at agg1 ----------------
extern "C" void kernel_launch(void* const* d_in, const int* in_sizes, int n_in,
                              void* d_out, int out_size) {
    const float* node_feat = (const float*)d_in[0];
    const void*  edge_idx  = d_in[1];
    const float* W1        = (const float*)d_in[2];
    const float* att_src1  = (const float*)d_in[3];
    const float* att_dst1  = (const float*)d_in[4];
    const float* b1        = (const float*)d_in[5];
    const float* W2        = (const float*)d_in[6];
    const float* att_src2  = (const float*)d_in[7];
    const float* att_dst2  = (const float*)d_in[8];
    const float* b2        = (const float*)d_in[9];
    float*       out       = (float*)d_out;

    const int N = in_sizes[0] / IN_CH;     // 50000
    const int E = in_sizes[1] / 2;         // 800000
    const int total = E + N;               // 850000

    int warpBlocks = (N * 32 + 255) / 256;

    cudaFuncSetAttribute(k_gemm1,
                         cudaFuncAttributeMaxDynamicSharedMemorySize, G1_SMEM);
    cudaFuncSetAttribute(k_gemm2,
                         cudaFuncAttributeMaxDynamicSharedMemorySize, G2_SMEM);

    // side stream + fork/join events (created per call; never destroyed —
    // kernel_launch runs only during correctness + capture, so the leak is
    // bounded and tiny; device work is identical every call)
    cudaStream_t s2;
    cudaStreamCreateWithFlags(&s2, cudaStreamNonBlocking);
    cudaEvent_t e0, e1;
    cudaEventCreateWithFlags(&e0, cudaEventDisableTiming);
    cudaEventCreateWithFlags(&e1, cudaEventDisableTiming);

    // fork: CSR chain on s2
    cudaEventRecord(e0, 0);
    cudaStreamWaitEvent(s2, e0, 0);
    k_zero_detect<<<(N + 255) / 256, 256, 0, s2>>>((const int*)edge_idx, E, N);
    k_hist   <<<(total + 255) / 256, 256, 0, s2>>>(edge_idx, E, total, N);
    k_scan   <<<1, 1024, 0, s2>>>(N);
    k_scatter<<<(total + 255) / 256, 256, 0, s2>>>(edge_idx, E, total, N);
    cudaEventRecord(e1, s2);

    // concurrent: gemm1 + fused att1 on the main (capture) stream
    k_gemm1<<<(N + 63) / 64, 256, G1_SMEM>>>(node_feat, W1, att_src1, att_dst1, N);

    // join, then the serial tail
    cudaStreamWaitEvent(0, e1, 0);
    k_agg1 <<<warpBlocks, 256>>>(b1, N);
    k_gemm2<<<(N + 127) / 128, 256, G2_SMEM>>>(W2, att_src2, att_dst2, N);
    k_agg2 <<<warpBlocks, 256>>>(b2, out, N);
}